// round 1
// baseline (speedup 1.0000x reference)
#include <cuda_runtime.h>
#include <cuda_bf16.h>
#include <math_constants.h>

// Problem constants (fixed by the reference)
#define NNODES 50000
#define NEDGES 800000
#define INF_   256
#define HID_   64
#define HEADS_ 4
#define CDIM_  64
#define SLOPE_ 0.2f
#define FEAT_  256   // HEADS*HID == HEADS*C == 256 (both layers)

// ---------------------------------------------------------------------------
// Scratch (static device globals; no allocation allowed)
// ---------------------------------------------------------------------------
__device__ float g_h1  [NNODES * FEAT_];
__device__ float g_out1[NNODES * FEAT_];
__device__ float g_h2  [NNODES * FEAT_];
__device__ float g_out2[NNODES * FEAT_];
__device__ float g_el  [NNODES * HEADS_];
__device__ float g_er  [NNODES * HEADS_];
__device__ float g_esc [NEDGES * HEADS_];
__device__ int   g_rowptr[NNODES + 1];

// ---------------------------------------------------------------------------
// SGEMM: C[M,256] = A[M,256] @ B[256,256], fp32, 64x64x16 tile, 4x4 per thread
// ---------------------------------------------------------------------------
#define BM 64
#define BN 64
#define BK 16
#define TM 4
#define TN 4

__global__ __launch_bounds__(256)
void sgemm256(const float* __restrict__ A, const float* __restrict__ B,
              float* __restrict__ C, int M) {
    __shared__ float As[BK][BM];
    __shared__ float Bs[BK][BN];

    const int tid     = threadIdx.x;
    const int rowBase = blockIdx.x * BM;
    const int colBase = blockIdx.y * BN;
    const int ty = tid >> 4;       // 0..15
    const int tx = tid & 15;       // 0..15

    float acc[TM][TN];
#pragma unroll
    for (int m = 0; m < TM; m++)
#pragma unroll
        for (int n = 0; n < TN; n++) acc[m][n] = 0.f;

    for (int k0 = 0; k0 < 256; k0 += BK) {
        // Load A tile: 64 rows x 16 cols (transposed into As[k][row])
#pragma unroll
        for (int i = 0; i < 4; i++) {
            int idx = tid + i * 256;
            int r = idx >> 4;      // 0..63
            int c = idx & 15;      // 0..15
            int gr = rowBase + r;
            As[c][r] = (gr < M) ? A[gr * 256 + k0 + c] : 0.f;
        }
        // Load B tile: 16 rows x 64 cols
#pragma unroll
        for (int i = 0; i < 4; i++) {
            int idx = tid + i * 256;
            int r = idx >> 6;      // 0..15
            int c = idx & 63;      // 0..63
            Bs[r][c] = B[(k0 + r) * 256 + colBase + c];
        }
        __syncthreads();

#pragma unroll
        for (int k = 0; k < BK; k++) {
            float ra[TM], rb[TN];
#pragma unroll
            for (int m = 0; m < TM; m++) ra[m] = As[k][ty * TM + m];
#pragma unroll
            for (int n = 0; n < TN; n++) rb[n] = Bs[k][tx * TN + n];
#pragma unroll
            for (int m = 0; m < TM; m++)
#pragma unroll
                for (int n = 0; n < TN; n++) acc[m][n] += ra[m] * rb[n];
        }
        __syncthreads();
    }

#pragma unroll
    for (int m = 0; m < TM; m++) {
        int gr = rowBase + ty * TM + m;
        if (gr < M) {
#pragma unroll
            for (int n = 0; n < TN; n++)
                C[gr * 256 + colBase + tx * TN + n] = acc[m][n];
        }
    }
}

// ---------------------------------------------------------------------------
// row_ptr via binary search (dst is sorted ascending)
// ---------------------------------------------------------------------------
__global__ void build_rowptr(const int* __restrict__ dst) {
    int i = blockIdx.x * blockDim.x + threadIdx.x;
    if (i > NNODES) return;
    int lo = 0, hi = NEDGES;
    while (lo < hi) {
        int mid = (lo + hi) >> 1;
        if (dst[mid] < i) lo = mid + 1; else hi = mid;
    }
    g_rowptr[i] = lo;
}

// ---------------------------------------------------------------------------
// Per-node attention dot products: el[n,h] = h[n,h,:]·al[h,:], er likewise.
// One block (128 thr = 4 warps) per node; warp w handles head w.
// ---------------------------------------------------------------------------
__global__ __launch_bounds__(128)
void attn_dots(const float* __restrict__ h,
               const float* __restrict__ al, const float* __restrict__ ar,
               float* __restrict__ el, float* __restrict__ er) {
    int n = blockIdx.x;
    int w = threadIdx.x >> 5;      // head
    int lane = threadIdx.x & 31;
    const float* hp = h + n * FEAT_ + w * 64;
    float v0 = hp[lane], v1 = hp[lane + 32];
    float sl = v0 * al[w * 64 + lane] + v1 * al[w * 64 + lane + 32];
    float sr = v0 * ar[w * 64 + lane] + v1 * ar[w * 64 + lane + 32];
#pragma unroll
    for (int off = 16; off > 0; off >>= 1) {
        sl += __shfl_down_sync(0xffffffffu, sl, off);
        sr += __shfl_down_sync(0xffffffffu, sr, off);
    }
    if (lane == 0) {
        el[n * HEADS_ + w] = sl;
        er[n * HEADS_ + w] = sr;
    }
}

// ---------------------------------------------------------------------------
// Edge scores: esc[e,h] = leaky_relu(el[src,h] + er[dst,h], 0.2)
// ---------------------------------------------------------------------------
__global__ void edge_score(const int* __restrict__ src, const int* __restrict__ dst,
                           const float* __restrict__ el, const float* __restrict__ er) {
    int e = blockIdx.x * blockDim.x + threadIdx.x;
    if (e >= NEDGES) return;
    int s = src[e], d = dst[e];
#pragma unroll
    for (int h = 0; h < HEADS_; h++) {
        float v = el[s * HEADS_ + h] + er[d * HEADS_ + h];
        g_esc[e * HEADS_ + h] = (v > 0.f) ? v : SLOPE_ * v;
    }
}

// ---------------------------------------------------------------------------
// Segment softmax over incoming edges (dst-sorted CSR). Thread per (n, h).
// Overwrites g_esc with alpha.
// ---------------------------------------------------------------------------
__global__ void seg_softmax() {
    int idx = blockIdx.x * blockDim.x + threadIdx.x;
    if (idx >= NNODES * HEADS_) return;
    int n = idx >> 2;
    int h = idx & 3;
    int b = g_rowptr[n], e1 = g_rowptr[n + 1];
    if (b == e1) return;
    float m = -CUDART_INF_F;
    for (int e = b; e < e1; e++) m = fmaxf(m, g_esc[e * HEADS_ + h]);
    float s = 0.f;
    for (int e = b; e < e1; e++) s += __expf(g_esc[e * HEADS_ + h] - m);
    float inv = 1.f / s;
    for (int e = b; e < e1; e++)
        g_esc[e * HEADS_ + h] = __expf(g_esc[e * HEADS_ + h] - m) * inv;
}

// ---------------------------------------------------------------------------
// Weighted aggregation: out[n,h,:] = sum_e alpha[e,h] * h[src[e],h,:] + bias
// One block (256 thr = 8 warps) per node; warp covers (head, half-of-64).
// ---------------------------------------------------------------------------
__global__ __launch_bounds__(256)
void aggregate(const float* __restrict__ hsrc, const int* __restrict__ src,
               const float* __restrict__ bias, float* __restrict__ out) {
    int n = blockIdx.x;
    int w = threadIdx.x >> 5;
    int lane = threadIdx.x & 31;
    int h = w & 3;
    int half = w >> 2;
    int col = h * 64 + half * 32 + lane;
    int b = g_rowptr[n], e1 = g_rowptr[n + 1];
    float acc = 0.f;
    for (int e = b; e < e1; e++) {
        float a = g_esc[e * HEADS_ + h];
        acc += a * hsrc[src[e] * FEAT_ + col];
    }
    out[n * FEAT_ + col] = acc + bias[col];
}

// ---------------------------------------------------------------------------
// Final head mean: d_out[n,c] = mean_h out2[n,h,c]   (bias already applied)
// ---------------------------------------------------------------------------
__global__ void head_mean(float* __restrict__ out) {
    int i = blockIdx.x * blockDim.x + threadIdx.x;
    if (i >= NNODES * CDIM_) return;
    int n = i >> 6;
    int c = i & 63;
    const float* p = g_out2 + n * FEAT_;
    out[i] = 0.25f * (p[c] + p[c + 64] + p[c + 128] + p[c + 192]);
}

// ---------------------------------------------------------------------------
// Launch
// ---------------------------------------------------------------------------
extern "C" void kernel_launch(void* const* d_in, const int* in_sizes, int n_in,
                              void* d_out, int out_size) {
    const float* x   = (const float*)d_in[0];
    const int*   src = (const int*)  d_in[1];
    const int*   dst = (const int*)  d_in[2];
    const float* W1  = (const float*)d_in[3];
    const float* al1 = (const float*)d_in[4];
    const float* ar1 = (const float*)d_in[5];
    const float* b1  = (const float*)d_in[6];
    const float* W2  = (const float*)d_in[7];
    const float* al2 = (const float*)d_in[8];
    const float* ar2 = (const float*)d_in[9];
    const float* b2  = (const float*)d_in[10];
    float* out = (float*)d_out;

    float *h1, *out1, *h2, *out2, *el, *er;
    cudaGetSymbolAddress((void**)&h1,   g_h1);
    cudaGetSymbolAddress((void**)&out1, g_out1);
    cudaGetSymbolAddress((void**)&h2,   g_h2);
    cudaGetSymbolAddress((void**)&out2, g_out2);
    cudaGetSymbolAddress((void**)&el,   g_el);
    cudaGetSymbolAddress((void**)&er,   g_er);

    dim3 gemmGrid((NNODES + BM - 1) / BM, 256 / BN);

    // CSR offsets (dst sorted)
    build_rowptr<<<(NNODES + 1 + 255) / 256, 256>>>(dst);

    // ---- Layer 1 ----
    sgemm256<<<gemmGrid, 256>>>(x, W1, h1, NNODES);
    attn_dots<<<NNODES, 128>>>(h1, al1, ar1, el, er);
    edge_score<<<(NEDGES + 255) / 256, 256>>>(src, dst, el, er);
    seg_softmax<<<(NNODES * HEADS_ + 255) / 256, 256>>>();
    aggregate<<<NNODES, 256>>>(h1, src, b1, out1);

    // ---- Layer 2 ----
    sgemm256<<<gemmGrid, 256>>>(out1, W2, h2, NNODES);
    attn_dots<<<NNODES, 128>>>(h2, al2, ar2, el, er);
    edge_score<<<(NEDGES + 255) / 256, 256>>>(src, dst, el, er);
    seg_softmax<<<(NNODES * HEADS_ + 255) / 256, 256>>>();
    aggregate<<<NNODES, 256>>>(h2, src, b2, out2);

    // ---- Head mean ----
    head_mean<<<(NNODES * CDIM_ + 255) / 256, 256>>>(out);
}

// round 3
// speedup vs baseline: 1.9800x; 1.9800x over previous
#include <cuda_runtime.h>
#include <cuda_bf16.h>
#include <math_constants.h>
#include <cstdint>

// Problem constants
#define NNODES 50000
#define NEDGES 800000
#define HEADS_ 4
#define CDIM_  64
#define SLOPE_ 0.2f
#define FEAT_  256
#define MTILES 391           // ceil(50000/128)

// ---------------------------------------------------------------------------
// Scratch
// ---------------------------------------------------------------------------
__device__ __align__(16) float g_h1  [NNODES * FEAT_];
__device__ __align__(16) float g_out1[NNODES * FEAT_];
__device__ __align__(16) float g_h2  [NNODES * FEAT_];
__device__ __align__(16) __nv_bfloat16 g_Ahi[NNODES * FEAT_];
__device__ __align__(16) __nv_bfloat16 g_Alo[NNODES * FEAT_];
__device__ __align__(16) __nv_bfloat16 g_Bhi[FEAT_ * FEAT_];
__device__ __align__(16) __nv_bfloat16 g_Blo[FEAT_ * FEAT_];
__device__ float g_el  [NNODES * HEADS_];
__device__ float g_er  [NNODES * HEADS_];
__device__ float g_esc [NEDGES * HEADS_];
__device__ int   g_rowptr[NNODES + 1];

// ---------------------------------------------------------------------------
// PTX helpers (portable ISA only: ldmatrix + mma.sync)
// ---------------------------------------------------------------------------
__device__ __forceinline__ uint32_t smem_u32(const void* p) {
    uint32_t a;
    asm("{ .reg .u64 t; cvta.to.shared.u64 t, %1; cvt.u32.u64 %0, t; }" : "=r"(a) : "l"(p));
    return a;
}
__device__ __forceinline__ void ldm4(uint32_t* r, uint32_t addr) {
    asm volatile("ldmatrix.sync.aligned.m8n8.x4.shared.b16 {%0,%1,%2,%3}, [%4];"
        : "=r"(r[0]), "=r"(r[1]), "=r"(r[2]), "=r"(r[3]) : "r"(addr));
}
__device__ __forceinline__ void mma16816(float* c, const uint32_t* a, uint32_t b0, uint32_t b1) {
    asm volatile("mma.sync.aligned.m16n8k16.row.col.f32.bf16.bf16.f32 "
        "{%0,%1,%2,%3}, {%4,%5,%6,%7}, {%8,%9}, {%0,%1,%2,%3};"
        : "+f"(c[0]), "+f"(c[1]), "+f"(c[2]), "+f"(c[3])
        : "r"(a[0]), "r"(a[1]), "r"(a[2]), "r"(a[3]), "r"(b0), "r"(b1));
}

// ---------------------------------------------------------------------------
// Split fp32 -> bf16 hi/lo (vectorized)
// ---------------------------------------------------------------------------
__global__ void split_a(const float* __restrict__ X,
                        __nv_bfloat16* __restrict__ hi,
                        __nv_bfloat16* __restrict__ lo, int n4) {
    int i = blockIdx.x * blockDim.x + threadIdx.x;
    if (i >= n4) return;
    float4 v = ((const float4*)X)[i];
    __nv_bfloat16 h0 = __float2bfloat16(v.x), h1 = __float2bfloat16(v.y);
    __nv_bfloat16 h2 = __float2bfloat16(v.z), h3 = __float2bfloat16(v.w);
    __nv_bfloat16 l0 = __float2bfloat16(v.x - __bfloat162float(h0));
    __nv_bfloat16 l1 = __float2bfloat16(v.y - __bfloat162float(h1));
    __nv_bfloat16 l2 = __float2bfloat16(v.z - __bfloat162float(h2));
    __nv_bfloat16 l3 = __float2bfloat16(v.w - __bfloat162float(h3));
    ((__nv_bfloat162*)hi)[2*i]   = __nv_bfloat162(h0, h1);
    ((__nv_bfloat162*)hi)[2*i+1] = __nv_bfloat162(h2, h3);
    ((__nv_bfloat162*)lo)[2*i]   = __nv_bfloat162(l0, l1);
    ((__nv_bfloat162*)lo)[2*i+1] = __nv_bfloat162(l2, l3);
}

// Transpose W[K=256,N=256] -> Bt[N,K] with hi/lo split (tiny)
__global__ void split_bT(const float* __restrict__ W,
                         __nv_bfloat16* __restrict__ hi,
                         __nv_bfloat16* __restrict__ lo) {
    int i = blockIdx.x * blockDim.x + threadIdx.x;
    if (i >= FEAT_ * FEAT_) return;
    int n = i >> 8, k = i & 255;
    float v = W[k * 256 + n];
    __nv_bfloat16 h = __float2bfloat16(v);
    hi[i] = h;
    lo[i] = __float2bfloat16(v - __bfloat162float(h));
}

// ---------------------------------------------------------------------------
// HMMA GEMM: C[M,256] = A@W via bf16x3 split. CTA tile 128x128, BK=32.
// 8 warps, each 32(M) x 64(N). ldmatrix from padded smem (stride 40 bf16).
// ---------------------------------------------------------------------------
#define BKC 32
#define STR 40              // smem row stride in bf16 (80 bytes, conflict-free)
#define TILEB (128 * STR)   // bf16 elements per tile matrix

__global__ __launch_bounds__(256, 1)
void gemm_bf16x3(const __nv_bfloat16* __restrict__ Ahi,
                 const __nv_bfloat16* __restrict__ Alo,
                 const __nv_bfloat16* __restrict__ Bhi,
                 const __nv_bfloat16* __restrict__ Blo,
                 float* __restrict__ C, int M) {
    __shared__ __nv_bfloat16 sAh[TILEB], sAl[TILEB], sBh[TILEB], sBl[TILEB];

    const int tid = threadIdx.x, wid = tid >> 5, lane = tid & 31;
    const int wm = wid & 3, wn = wid >> 2;       // warp row/col block
    const int row0 = blockIdx.x * 128;
    const int col0 = blockIdx.y * 128;

    float acc[2][8][4];
#pragma unroll
    for (int mt = 0; mt < 2; mt++)
#pragma unroll
        for (int nt = 0; nt < 8; nt++)
#pragma unroll
            for (int q = 0; q < 4; q++) acc[mt][nt][q] = 0.f;

    const uint32_t sAh_u = smem_u32(sAh), sAl_u = smem_u32(sAl);
    const uint32_t sBh_u = smem_u32(sBh), sBl_u = smem_u32(sBl);

    // ldmatrix lane addressing: row = lane & 15, k-half = (lane >> 4) * 8
    const int lrow = lane & 15;
    const int lkof = (lane >> 4) * 8;

    for (int kc = 0; kc < 8; kc++) {
        // Stage A (2 uint4/thread/matrix) and B
#pragma unroll
        for (int it = 0; it < 2; it++) {
            int idx = tid + it * 256;
            int r = idx >> 2, q = idx & 3;          // 128 rows x 4 quads
            int so = r * STR + q * 8;               // bf16 offset (16B quad)
            int gr = row0 + r;
            uint4 vh = make_uint4(0,0,0,0), vl = vh;
            if (gr < M) {
                vh = ((const uint4*)(Ahi + (size_t)gr * 256 + kc * BKC))[q];
                vl = ((const uint4*)(Alo + (size_t)gr * 256 + kc * BKC))[q];
            }
            *(uint4*)(sAh + so) = vh;
            *(uint4*)(sAl + so) = vl;
            int gn = col0 + r;
            *(uint4*)(sBh + so) = ((const uint4*)(Bhi + (size_t)gn * 256 + kc * BKC))[q];
            *(uint4*)(sBl + so) = ((const uint4*)(Blo + (size_t)gn * 256 + kc * BKC))[q];
        }
        __syncthreads();

#pragma unroll
        for (int ks = 0; ks < 2; ks++) {
            const uint32_t kbyte = (uint32_t)((ks * 16 + lkof) * 2);
            // A fragments (2 m-tiles, hi+lo)
            uint32_t ah[2][4], al[2][4];
#pragma unroll
            for (int mt = 0; mt < 2; mt++) {
                uint32_t ro = (uint32_t)((wm * 32 + mt * 16 + lrow) * STR * 2) + kbyte;
                ldm4(ah[mt], sAh_u + ro);
                ldm4(al[mt], sAl_u + ro);
            }
            // B fragments (8 n-tiles as 4 pair-loads, hi+lo)
            uint32_t bh[4][4], bl[4][4];
#pragma unroll
            for (int p = 0; p < 4; p++) {
                uint32_t ro = (uint32_t)((wn * 64 + p * 16 + lrow) * STR * 2) + kbyte;
                ldm4(bh[p], sBh_u + ro);
                ldm4(bl[p], sBl_u + ro);
            }
#pragma unroll
            for (int mt = 0; mt < 2; mt++)
#pragma unroll
                for (int nt = 0; nt < 8; nt++) {
                    int p = nt >> 1, o = nt & 1;
                    mma16816(acc[mt][nt], ah[mt], bh[p][o], bh[p][2 + o]);   // hi*hi
                    mma16816(acc[mt][nt], ah[mt], bl[p][o], bl[p][2 + o]);   // hi*lo
                    mma16816(acc[mt][nt], al[mt], bh[p][o], bh[p][2 + o]);   // lo*hi
                }
        }
        __syncthreads();
    }

    // Epilogue: direct fp32 stores
    const int qrow = lane >> 2, qcol = (lane & 3) * 2;
#pragma unroll
    for (int mt = 0; mt < 2; mt++) {
        int r0 = row0 + wm * 32 + mt * 16 + qrow;
#pragma unroll
        for (int nt = 0; nt < 8; nt++) {
            int c = col0 + wn * 64 + nt * 8 + qcol;
            if (r0 < M)
                *(float2*)(C + (size_t)r0 * 256 + c) = make_float2(acc[mt][nt][0], acc[mt][nt][1]);
            if (r0 + 8 < M)
                *(float2*)(C + (size_t)(r0 + 8) * 256 + c) = make_float2(acc[mt][nt][2], acc[mt][nt][3]);
        }
    }
}

// ---------------------------------------------------------------------------
// row_ptr via binary search (dst sorted ascending)
// ---------------------------------------------------------------------------
__global__ void build_rowptr(const int* __restrict__ dst) {
    int i = blockIdx.x * blockDim.x + threadIdx.x;
    if (i > NNODES) return;
    int lo = 0, hi = NEDGES;
    while (lo < hi) {
        int mid = (lo + hi) >> 1;
        if (dst[mid] < i) lo = mid + 1; else hi = mid;
    }
    g_rowptr[i] = lo;
}

// ---------------------------------------------------------------------------
// Per-node attention dots
// ---------------------------------------------------------------------------
__global__ __launch_bounds__(128)
void attn_dots(const float* __restrict__ h,
               const float* __restrict__ al, const float* __restrict__ ar,
               float* __restrict__ el, float* __restrict__ er) {
    int n = blockIdx.x;
    int w = threadIdx.x >> 5, lane = threadIdx.x & 31;
    const float* hp = h + (size_t)n * FEAT_ + w * 64;
    float v0 = hp[lane], v1 = hp[lane + 32];
    float sl = v0 * al[w * 64 + lane] + v1 * al[w * 64 + lane + 32];
    float sr = v0 * ar[w * 64 + lane] + v1 * ar[w * 64 + lane + 32];
#pragma unroll
    for (int off = 16; off > 0; off >>= 1) {
        sl += __shfl_down_sync(0xffffffffu, sl, off);
        sr += __shfl_down_sync(0xffffffffu, sr, off);
    }
    if (lane == 0) {
        el[n * HEADS_ + w] = sl;
        er[n * HEADS_ + w] = sr;
    }
}

__global__ void edge_score(const int* __restrict__ src, const int* __restrict__ dst,
                           const float* __restrict__ el, const float* __restrict__ er) {
    int e = blockIdx.x * blockDim.x + threadIdx.x;
    if (e >= NEDGES) return;
    int s = src[e], d = dst[e];
#pragma unroll
    for (int h = 0; h < HEADS_; h++) {
        float v = el[s * HEADS_ + h] + er[d * HEADS_ + h];
        g_esc[e * HEADS_ + h] = (v > 0.f) ? v : SLOPE_ * v;
    }
}

__global__ void seg_softmax() {
    int idx = blockIdx.x * blockDim.x + threadIdx.x;
    if (idx >= NNODES * HEADS_) return;
    int n = idx >> 2, h = idx & 3;
    int b = g_rowptr[n], e1 = g_rowptr[n + 1];
    if (b == e1) return;
    float m = -CUDART_INF_F;
    for (int e = b; e < e1; e++) m = fmaxf(m, g_esc[e * HEADS_ + h]);
    float s = 0.f;
    for (int e = b; e < e1; e++) s += __expf(g_esc[e * HEADS_ + h] - m);
    float inv = 1.f / s;
    for (int e = b; e < e1; e++)
        g_esc[e * HEADS_ + h] = __expf(g_esc[e * HEADS_ + h] - m) * inv;
}

// ---------------------------------------------------------------------------
// Aggregation: 64 threads/node, float4 per thread
// ---------------------------------------------------------------------------
__global__ __launch_bounds__(64)
void aggregate64(const float* __restrict__ hsrc, const int* __restrict__ src,
                 const float* __restrict__ bias, float* __restrict__ out) {
    int n = blockIdx.x, tid = threadIdx.x;
    int h = tid >> 4;
    int b = g_rowptr[n], e1 = g_rowptr[n + 1];
    float4 acc = make_float4(0.f, 0.f, 0.f, 0.f);
    for (int e = b; e < e1; e++) {
        float a = g_esc[e * HEADS_ + h];
        float4 v = ((const float4*)(hsrc + (size_t)src[e] * FEAT_))[tid];
        acc.x += a * v.x; acc.y += a * v.y; acc.z += a * v.z; acc.w += a * v.w;
    }
    float4 bb = ((const float4*)bias)[tid];
    acc.x += bb.x; acc.y += bb.y; acc.z += bb.z; acc.w += bb.w;
    ((float4*)(out + (size_t)n * FEAT_))[tid] = acc;
}

// Layer-2 aggregation fused with head-mean
__global__ __launch_bounds__(64)
void aggregate64_mean(const float* __restrict__ hsrc, const int* __restrict__ src,
                      const float* __restrict__ bias, float* __restrict__ out) {
    __shared__ float4 sh[64];
    int n = blockIdx.x, tid = threadIdx.x;
    int h = tid >> 4;
    int b = g_rowptr[n], e1 = g_rowptr[n + 1];
    float4 acc = make_float4(0.f, 0.f, 0.f, 0.f);
    for (int e = b; e < e1; e++) {
        float a = g_esc[e * HEADS_ + h];
        float4 v = ((const float4*)(hsrc + (size_t)src[e] * FEAT_))[tid];
        acc.x += a * v.x; acc.y += a * v.y; acc.z += a * v.z; acc.w += a * v.w;
    }
    float4 bb = ((const float4*)bias)[tid];
    acc.x += bb.x; acc.y += bb.y; acc.z += bb.z; acc.w += bb.w;
    sh[tid] = acc;
    __syncthreads();
    if (tid < 16) {
        float4 a = sh[tid], b4 = sh[tid + 16], c = sh[tid + 32], d = sh[tid + 48];
        float4 r = make_float4(0.25f * (a.x + b4.x + c.x + d.x),
                               0.25f * (a.y + b4.y + c.y + d.y),
                               0.25f * (a.z + b4.z + c.z + d.z),
                               0.25f * (a.w + b4.w + c.w + d.w));
        ((float4*)(out + (size_t)n * CDIM_))[tid] = r;
    }
}

// ---------------------------------------------------------------------------
// Launch
// ---------------------------------------------------------------------------
extern "C" void kernel_launch(void* const* d_in, const int* in_sizes, int n_in,
                              void* d_out, int out_size) {
    const float* x   = (const float*)d_in[0];
    const int*   src = (const int*)  d_in[1];
    const int*   dst = (const int*)  d_in[2];
    const float* W1  = (const float*)d_in[3];
    const float* al1 = (const float*)d_in[4];
    const float* ar1 = (const float*)d_in[5];
    const float* b1  = (const float*)d_in[6];
    const float* W2  = (const float*)d_in[7];
    const float* al2 = (const float*)d_in[8];
    const float* ar2 = (const float*)d_in[9];
    const float* b2  = (const float*)d_in[10];
    float* out = (float*)d_out;

    float *h1, *out1, *h2, *el, *er;
    __nv_bfloat16 *Ahi, *Alo, *Bhi, *Blo;
    cudaGetSymbolAddress((void**)&h1,   g_h1);
    cudaGetSymbolAddress((void**)&out1, g_out1);
    cudaGetSymbolAddress((void**)&h2,   g_h2);
    cudaGetSymbolAddress((void**)&el,   g_el);
    cudaGetSymbolAddress((void**)&er,   g_er);
    cudaGetSymbolAddress((void**)&Ahi,  g_Ahi);
    cudaGetSymbolAddress((void**)&Alo,  g_Alo);
    cudaGetSymbolAddress((void**)&Bhi,  g_Bhi);
    cudaGetSymbolAddress((void**)&Blo,  g_Blo);

    const int n4 = NNODES * FEAT_ / 4;
    dim3 gemmGrid(MTILES, 2);

    build_rowptr<<<(NNODES + 256) / 256, 256>>>(dst);

    // ---- Layer 1 ----
    split_bT<<<(FEAT_ * FEAT_ + 255) / 256, 256>>>(W1, Bhi, Blo);
    split_a<<<(n4 + 255) / 256, 256>>>(x, Ahi, Alo, n4);
    gemm_bf16x3<<<gemmGrid, 256>>>(Ahi, Alo, Bhi, Blo, h1, NNODES);
    attn_dots<<<NNODES, 128>>>(h1, al1, ar1, el, er);
    edge_score<<<(NEDGES + 255) / 256, 256>>>(src, dst, el, er);
    seg_softmax<<<(NNODES * HEADS_ + 255) / 256, 256>>>();
    aggregate64<<<NNODES, 64>>>(h1, src, b1, out1);

    // ---- Layer 2 ----
    split_bT<<<(FEAT_ * FEAT_ + 255) / 256, 256>>>(W2, Bhi, Blo);
    split_a<<<(n4 + 255) / 256, 256>>>(out1, Ahi, Alo, n4);
    gemm_bf16x3<<<gemmGrid, 256>>>(Ahi, Alo, Bhi, Blo, h2, NNODES);
    attn_dots<<<NNODES, 128>>>(h2, al2, ar2, el, er);
    edge_score<<<(NEDGES + 255) / 256, 256>>>(src, dst, el, er);
    seg_softmax<<<(NNODES * HEADS_ + 255) / 256, 256>>>();
    aggregate64_mean<<<NNODES, 64>>>(h2, src, b2, out);
}

// round 4
// speedup vs baseline: 2.3413x; 1.1825x over previous
#include <cuda_runtime.h>
#include <cuda_bf16.h>
#include <math_constants.h>
#include <cstdint>

// Problem constants
#define NNODES 50000
#define NEDGES 800000
#define HEADS_ 4
#define CDIM_  64
#define SLOPE_ 0.2f
#define FEAT_  256
#define MTILES 391           // ceil(50000/128)
#define ECAP   192           // cached-edge capacity per node (avg deg 16)

// ---------------------------------------------------------------------------
// Scratch
// ---------------------------------------------------------------------------
__device__ __align__(16) float g_h1  [NNODES * FEAT_];
__device__ __align__(16) float g_out1[NNODES * FEAT_];
__device__ __align__(16) float g_h2  [NNODES * FEAT_];
__device__ __align__(16) __nv_bfloat16 g_Bhi[FEAT_ * FEAT_];
__device__ __align__(16) __nv_bfloat16 g_Blo[FEAT_ * FEAT_];
__device__ __align__(16) float g_el  [NNODES * HEADS_];
__device__ __align__(16) float g_er  [NNODES * HEADS_];
__device__ int   g_rowptr[NNODES + 1];

// ---------------------------------------------------------------------------
// PTX helpers (portable ISA: ldmatrix + mma.sync + cp.async)
// ---------------------------------------------------------------------------
__device__ __forceinline__ uint32_t smem_u32(const void* p) {
    uint32_t a;
    asm("{ .reg .u64 t; cvta.to.shared.u64 t, %1; cvt.u32.u64 %0, t; }" : "=r"(a) : "l"(p));
    return a;
}
__device__ __forceinline__ void ldm4(uint32_t* r, uint32_t addr) {
    asm volatile("ldmatrix.sync.aligned.m8n8.x4.shared.b16 {%0,%1,%2,%3}, [%4];"
        : "=r"(r[0]), "=r"(r[1]), "=r"(r[2]), "=r"(r[3]) : "r"(addr));
}
__device__ __forceinline__ void mma16816(float* c, const uint32_t* a, uint32_t b0, uint32_t b1) {
    asm volatile("mma.sync.aligned.m16n8k16.row.col.f32.bf16.bf16.f32 "
        "{%0,%1,%2,%3}, {%4,%5,%6,%7}, {%8,%9}, {%0,%1,%2,%3};"
        : "+f"(c[0]), "+f"(c[1]), "+f"(c[2]), "+f"(c[3])
        : "r"(a[0]), "r"(a[1]), "r"(a[2]), "r"(a[3]), "r"(b0), "r"(b1));
}
#define CP16(dst, src) asm volatile("cp.async.cg.shared.global [%0], [%1], 16;" :: "r"(dst), "l"(src))
#define CP_COMMIT()    asm volatile("cp.async.commit_group;" ::: "memory")
#define CP_WAIT(n)     asm volatile("cp.async.wait_group %0;" :: "n"(n) : "memory")

__device__ __forceinline__ uint32_t packbf2(float a, float b) {
    __nv_bfloat162 h2 = __nv_bfloat162(__float2bfloat16(a), __float2bfloat16(b));
    return *(uint32_t*)&h2;
}

// ---------------------------------------------------------------------------
// Transpose W[K=256,N=256] -> Bt[N,K] with hi/lo split (tiny)
// ---------------------------------------------------------------------------
__global__ void split_bT(const float* __restrict__ W,
                         __nv_bfloat16* __restrict__ hi,
                         __nv_bfloat16* __restrict__ lo) {
    int i = blockIdx.x * blockDim.x + threadIdx.x;
    if (i >= FEAT_ * FEAT_) return;
    int n = i >> 8, k = i & 255;
    float v = W[k * 256 + n];
    __nv_bfloat16 h = __float2bfloat16(v);
    hi[i] = h;
    lo[i] = __float2bfloat16(v - __bfloat162float(h));
}

// ---------------------------------------------------------------------------
// HMMA GEMM (bf16x3 split, fp32 A input, fused hi/lo convert, double-buffered)
// CTA tile 128x128, BK=32, 8 warps each 32x64.
// ---------------------------------------------------------------------------
#define BKC 32
#define STR 40              // smem row stride in bf16 (80 bytes, conflict-free)
#define TILEB (128 * STR)   // bf16 elements per tile matrix per buffer

__global__ __launch_bounds__(256, 1)
void gemm_bf16x3(const float* __restrict__ A,
                 const __nv_bfloat16* __restrict__ Bhi,
                 const __nv_bfloat16* __restrict__ Blo,
                 float* __restrict__ C, int M) {
    __shared__ __nv_bfloat16 sAh[2][TILEB], sAl[2][TILEB], sBh[2][TILEB], sBl[2][TILEB];

    const int tid = threadIdx.x, wid = tid >> 5, lane = tid & 31;
    const int wm = wid & 3, wn = wid >> 2;
    const int row0 = blockIdx.x * 128;
    const int col0 = blockIdx.y * 128;

    // staging thread mapping: r = tid>>1 (0..127), half = tid&1
    const int sr = tid >> 1, shalf = tid & 1;
    const int agr = row0 + sr;                      // global A row
    const int bgr = col0 + sr;                      // global B row (N index)
    const uint32_t sOffB = (uint32_t)(sr * STR * 2 + shalf * 32);  // bytes

    float acc[2][8][4];
#pragma unroll
    for (int mt = 0; mt < 2; mt++)
#pragma unroll
        for (int nt = 0; nt < 8; nt++)
#pragma unroll
            for (int q = 0; q < 4; q++) acc[mt][nt][q] = 0.f;

    // --- staging lambdas ---
    auto stageB = [&](int kc, int buf) {
        const char* srcH = (const char*)(Bhi + (size_t)bgr * 256 + kc * BKC) + shalf * 32;
        const char* srcL = (const char*)(Blo + (size_t)bgr * 256 + kc * BKC) + shalf * 32;
        uint32_t dH = smem_u32(sBh[buf]) + sOffB;
        uint32_t dL = smem_u32(sBl[buf]) + sOffB;
        CP16(dH, srcH); CP16(dH + 16, srcH + 16);
        CP16(dL, srcL); CP16(dL + 16, srcL + 16);
    };
    float fv[16];
    auto loadA = [&](int kc) {
        const float4* ap = (const float4*)(A + (size_t)agr * 256 + kc * BKC) + shalf * 4;
        if (agr < M) {
#pragma unroll
            for (int j = 0; j < 4; j++) *(float4*)(fv + 4 * j) = ap[j];
        } else {
#pragma unroll
            for (int j = 0; j < 16; j++) fv[j] = 0.f;
        }
    };
    auto storeA = [&](int buf) {
        uint32_t hiw[8], low[8];
#pragma unroll
        for (int p = 0; p < 8; p++) {
            float a = fv[2 * p], b = fv[2 * p + 1];
            float ha = __bfloat162float(__float2bfloat16(a));
            float hb = __bfloat162float(__float2bfloat16(b));
            hiw[p] = packbf2(a, b);
            low[p] = packbf2(a - ha, b - hb);
        }
        __nv_bfloat16* dh = sAh[buf] + sr * STR + shalf * 16;
        __nv_bfloat16* dl = sAl[buf] + sr * STR + shalf * 16;
        *(uint4*)dh = make_uint4(hiw[0], hiw[1], hiw[2], hiw[3]);
        *(uint4*)(dh + 8) = make_uint4(hiw[4], hiw[5], hiw[6], hiw[7]);
        *(uint4*)dl = make_uint4(low[0], low[1], low[2], low[3]);
        *(uint4*)(dl + 8) = make_uint4(low[4], low[5], low[6], low[7]);
    };

    // ldmatrix lane addressing
    const int lrow = lane & 15;
    const int lkof = (lane >> 4) * 8;

    // --- prologue: stage kc=0 into buf 0 ---
    stageB(0, 0); CP_COMMIT();
    loadA(0); storeA(0);

    for (int kc = 0; kc < 8; kc++) {
        const int buf = kc & 1;
        if (kc < 7) {
            stageB(kc + 1, buf ^ 1); CP_COMMIT();
            loadA(kc + 1);
        }
        if (kc < 7) { CP_WAIT(1); } else { CP_WAIT(0); }
        __syncthreads();

        const uint32_t sAh_u = smem_u32(sAh[buf]), sAl_u = smem_u32(sAl[buf]);
        const uint32_t sBh_u = smem_u32(sBh[buf]), sBl_u = smem_u32(sBl[buf]);
#pragma unroll
        for (int ks = 0; ks < 2; ks++) {
            const uint32_t kbyte = (uint32_t)((ks * 16 + lkof) * 2);
            uint32_t ah[2][4], al[2][4];
#pragma unroll
            for (int mt = 0; mt < 2; mt++) {
                uint32_t ro = (uint32_t)((wm * 32 + mt * 16 + lrow) * STR * 2) + kbyte;
                ldm4(ah[mt], sAh_u + ro);
                ldm4(al[mt], sAl_u + ro);
            }
            uint32_t bh[4][4], bl[4][4];
#pragma unroll
            for (int p = 0; p < 4; p++) {
                uint32_t ro = (uint32_t)((wn * 64 + p * 16 + lrow) * STR * 2) + kbyte;
                ldm4(bh[p], sBh_u + ro);
                ldm4(bl[p], sBl_u + ro);
            }
#pragma unroll
            for (int mt = 0; mt < 2; mt++)
#pragma unroll
                for (int nt = 0; nt < 8; nt++) {
                    int p = nt >> 1, o = nt & 1;
                    mma16816(acc[mt][nt], ah[mt], bh[p][o], bh[p][2 + o]);
                    mma16816(acc[mt][nt], ah[mt], bl[p][o], bl[p][2 + o]);
                    mma16816(acc[mt][nt], al[mt], bh[p][o], bh[p][2 + o]);
                }
        }
        __syncthreads();
        if (kc < 7) storeA(buf ^ 1);
    }

    // Epilogue
    const int qrow = lane >> 2, qcol = (lane & 3) * 2;
#pragma unroll
    for (int mt = 0; mt < 2; mt++) {
        int r0 = row0 + wm * 32 + mt * 16 + qrow;
#pragma unroll
        for (int nt = 0; nt < 8; nt++) {
            int c = col0 + wn * 64 + nt * 8 + qcol;
            if (r0 < M)
                *(float2*)(C + (size_t)r0 * 256 + c) = make_float2(acc[mt][nt][0], acc[mt][nt][1]);
            if (r0 + 8 < M)
                *(float2*)(C + (size_t)(r0 + 8) * 256 + c) = make_float2(acc[mt][nt][2], acc[mt][nt][3]);
        }
    }
}

// ---------------------------------------------------------------------------
// row_ptr via binary search (dst sorted ascending)
// ---------------------------------------------------------------------------
__global__ void build_rowptr(const int* __restrict__ dst) {
    int i = blockIdx.x * blockDim.x + threadIdx.x;
    if (i > NNODES) return;
    int lo = 0, hi = NEDGES;
    while (lo < hi) {
        int mid = (lo + hi) >> 1;
        if (dst[mid] < i) lo = mid + 1; else hi = mid;
    }
    g_rowptr[i] = lo;
}

// ---------------------------------------------------------------------------
// Per-node attention dots
// ---------------------------------------------------------------------------
__global__ __launch_bounds__(128)
void attn_dots(const float* __restrict__ h,
               const float* __restrict__ al, const float* __restrict__ ar,
               float* __restrict__ el, float* __restrict__ er) {
    int n = blockIdx.x;
    int w = threadIdx.x >> 5, lane = threadIdx.x & 31;
    const float* hp = h + (size_t)n * FEAT_ + w * 64;
    float v0 = hp[lane], v1 = hp[lane + 32];
    float sl = v0 * al[w * 64 + lane] + v1 * al[w * 64 + lane + 32];
    float sr = v0 * ar[w * 64 + lane] + v1 * ar[w * 64 + lane + 32];
#pragma unroll
    for (int off = 16; off > 0; off >>= 1) {
        sl += __shfl_down_sync(0xffffffffu, sl, off);
        sr += __shfl_down_sync(0xffffffffu, sr, off);
    }
    if (lane == 0) {
        el[n * HEADS_ + w] = sl;
        er[n * HEADS_ + w] = sr;
    }
}

// ---------------------------------------------------------------------------
// Fused edge kernel: score + segment softmax + aggregate (+ optional head mean)
// 64 threads/node. thread tid owns column quad tid (head = tid>>4).
// ---------------------------------------------------------------------------
__device__ __forceinline__ float lrelu(float v) { return v > 0.f ? v : SLOPE_ * v; }

template <bool MEAN>
__global__ __launch_bounds__(64)
void edge_fused(const float* __restrict__ hsrc, const int* __restrict__ src,
                const float* __restrict__ el, const float* __restrict__ er,
                const float* __restrict__ bias, float* __restrict__ out) {
    __shared__ float4 s_sc[ECAP];
    __shared__ int    s_src[ECAP];
    __shared__ float4 s_red[64];

    const int n = blockIdx.x, tid = threadIdx.x;
    const int h = tid >> 4, l16 = tid & 15;
    const int b = g_rowptr[n], e1 = g_rowptr[n + 1];
    const int deg = e1 - b;
    const float4 ern = ((const float4*)er)[n];
    const float ern_h = (&ern.x)[h];

    float4 acc = make_float4(0.f, 0.f, 0.f, 0.f);

    if (deg > 0 && deg <= ECAP) {
        // Phase 1: scores into smem
        for (int i = tid; i < deg; i += 64) {
            int s = src[b + i];
            s_src[i] = s;
            float4 e4 = ((const float4*)el)[s];
            s_sc[i] = make_float4(lrelu(e4.x + ern.x), lrelu(e4.y + ern.y),
                                  lrelu(e4.z + ern.z), lrelu(e4.w + ern.w));
        }
        __syncthreads();
        // Phase 2: per-head max & sum (16 lanes per head)
        float m = -CUDART_INF_F;
        for (int i = l16; i < deg; i += 16) m = fmaxf(m, (&s_sc[i].x)[h]);
#pragma unroll
        for (int off = 8; off > 0; off >>= 1)
            m = fmaxf(m, __shfl_xor_sync(0xffffffffu, m, off));
        float s = 0.f;
        for (int i = l16; i < deg; i += 16) s += __expf((&s_sc[i].x)[h] - m);
#pragma unroll
        for (int off = 8; off > 0; off >>= 1)
            s += __shfl_xor_sync(0xffffffffu, s, off);
        float inv = 1.f / s;
        for (int i = l16; i < deg; i += 16)
            (&s_sc[i].x)[h] = __expf((&s_sc[i].x)[h] - m) * inv;
        __syncthreads();
        // Phase 3: aggregate
        for (int i = 0; i < deg; i++) {
            float a = (&s_sc[i].x)[h];
            float4 v = ((const float4*)(hsrc + (size_t)s_src[i] * FEAT_))[tid];
            acc.x += a * v.x; acc.y += a * v.y; acc.z += a * v.z; acc.w += a * v.w;
        }
    } else if (deg > ECAP) {
        // Fallback: recompute-based (no caching)
        float m = -CUDART_INF_F;
        for (int i = l16; i < deg; i += 16) {
            int sidx = src[b + i];
            m = fmaxf(m, lrelu(el[sidx * 4 + h] + ern_h));
        }
#pragma unroll
        for (int off = 8; off > 0; off >>= 1)
            m = fmaxf(m, __shfl_xor_sync(0xffffffffu, m, off));
        float s = 0.f;
        for (int i = l16; i < deg; i += 16) {
            int sidx = src[b + i];
            s += __expf(lrelu(el[sidx * 4 + h] + ern_h) - m);
        }
#pragma unroll
        for (int off = 8; off > 0; off >>= 1)
            s += __shfl_xor_sync(0xffffffffu, s, off);
        float inv = 1.f / s;
        for (int i = 0; i < deg; i++) {
            int sidx = src[b + i];
            float a = __expf(lrelu(el[sidx * 4 + h] + ern_h) - m) * inv;
            float4 v = ((const float4*)(hsrc + (size_t)sidx * FEAT_))[tid];
            acc.x += a * v.x; acc.y += a * v.y; acc.z += a * v.z; acc.w += a * v.w;
        }
    }

    float4 bb = ((const float4*)bias)[tid];
    acc.x += bb.x; acc.y += bb.y; acc.z += bb.z; acc.w += bb.w;

    if (!MEAN) {
        ((float4*)(out + (size_t)n * FEAT_))[tid] = acc;
    } else {
        s_red[tid] = acc;
        __syncthreads();
        if (tid < 16) {
            float4 a = s_red[tid], b4 = s_red[tid + 16], c = s_red[tid + 32], d = s_red[tid + 48];
            float4 r = make_float4(0.25f * (a.x + b4.x + c.x + d.x),
                                   0.25f * (a.y + b4.y + c.y + d.y),
                                   0.25f * (a.z + b4.z + c.z + d.z),
                                   0.25f * (a.w + b4.w + c.w + d.w));
            ((float4*)(out + (size_t)n * CDIM_))[tid] = r;
        }
    }
}

// ---------------------------------------------------------------------------
// Launch
// ---------------------------------------------------------------------------
extern "C" void kernel_launch(void* const* d_in, const int* in_sizes, int n_in,
                              void* d_out, int out_size) {
    const float* x   = (const float*)d_in[0];
    const int*   src = (const int*)  d_in[1];
    const int*   dst = (const int*)  d_in[2];
    const float* W1  = (const float*)d_in[3];
    const float* al1 = (const float*)d_in[4];
    const float* ar1 = (const float*)d_in[5];
    const float* b1  = (const float*)d_in[6];
    const float* W2  = (const float*)d_in[7];
    const float* al2 = (const float*)d_in[8];
    const float* ar2 = (const float*)d_in[9];
    const float* b2  = (const float*)d_in[10];
    float* out = (float*)d_out;

    float *h1, *out1, *h2, *el, *er;
    __nv_bfloat16 *Bhi, *Blo;
    cudaGetSymbolAddress((void**)&h1,   g_h1);
    cudaGetSymbolAddress((void**)&out1, g_out1);
    cudaGetSymbolAddress((void**)&h2,   g_h2);
    cudaGetSymbolAddress((void**)&el,   g_el);
    cudaGetSymbolAddress((void**)&er,   g_er);
    cudaGetSymbolAddress((void**)&Bhi,  g_Bhi);
    cudaGetSymbolAddress((void**)&Blo,  g_Blo);

    dim3 gemmGrid(MTILES, 2);

    build_rowptr<<<(NNODES + 256) / 256, 256>>>(dst);

    // ---- Layer 1 ----
    split_bT<<<(FEAT_ * FEAT_ + 255) / 256, 256>>>(W1, Bhi, Blo);
    gemm_bf16x3<<<gemmGrid, 256>>>(x, Bhi, Blo, h1, NNODES);
    attn_dots<<<NNODES, 128>>>(h1, al1, ar1, el, er);
    edge_fused<false><<<NNODES, 64>>>(h1, src, el, er, b1, out1);

    // ---- Layer 2 ----
    split_bT<<<(FEAT_ * FEAT_ + 255) / 256, 256>>>(W2, Bhi, Blo);
    gemm_bf16x3<<<gemmGrid, 256>>>(out1, Bhi, Blo, h2, NNODES);
    attn_dots<<<NNODES, 128>>>(h2, al2, ar2, el, er);
    edge_fused<true><<<NNODES, 64>>>(h2, src, el, er, b2, out);
}

// round 5
// speedup vs baseline: 2.6595x; 1.1359x over previous
#include <cuda_runtime.h>
#include <cuda_bf16.h>
#include <math_constants.h>
#include <cstdint>

// Problem constants
#define NNODES 50000
#define NEDGES 800000
#define HEADS_ 4
#define CDIM_  64
#define SLOPE_ 0.2f
#define FEAT_  256
#define MTILES 391           // ceil(50000/128)
#define ECAP   192           // cached-edge capacity per node (avg deg 16)

// ---------------------------------------------------------------------------
// Scratch
// ---------------------------------------------------------------------------
__device__ __align__(16) float g_h1  [NNODES * FEAT_];
__device__ __align__(16) float g_out1[NNODES * FEAT_];
__device__ __align__(16) float g_h2  [NNODES * FEAT_];
__device__ __align__(16) __nv_bfloat16 g_Bhi[FEAT_ * FEAT_];
__device__ __align__(16) __nv_bfloat16 g_Blo[FEAT_ * FEAT_];
__device__ __align__(16) float g_el  [NNODES * HEADS_];
__device__ __align__(16) float g_er  [NNODES * HEADS_];
__device__ int   g_rowptr[NNODES + 1];

// ---------------------------------------------------------------------------
// PTX helpers (portable ISA: ldmatrix + mma.sync + cp.async)
// ---------------------------------------------------------------------------
__device__ __forceinline__ uint32_t smem_u32(const void* p) {
    uint32_t a;
    asm("{ .reg .u64 t; cvta.to.shared.u64 t, %1; cvt.u32.u64 %0, t; }" : "=r"(a) : "l"(p));
    return a;
}
__device__ __forceinline__ void ldm4(uint32_t* r, uint32_t addr) {
    asm volatile("ldmatrix.sync.aligned.m8n8.x4.shared.b16 {%0,%1,%2,%3}, [%4];"
        : "=r"(r[0]), "=r"(r[1]), "=r"(r[2]), "=r"(r[3]) : "r"(addr));
}
__device__ __forceinline__ void mma16816(float* c, const uint32_t* a, uint32_t b0, uint32_t b1) {
    asm volatile("mma.sync.aligned.m16n8k16.row.col.f32.bf16.bf16.f32 "
        "{%0,%1,%2,%3}, {%4,%5,%6,%7}, {%8,%9}, {%0,%1,%2,%3};"
        : "+f"(c[0]), "+f"(c[1]), "+f"(c[2]), "+f"(c[3])
        : "r"(a[0]), "r"(a[1]), "r"(a[2]), "r"(a[3]), "r"(b0), "r"(b1));
}
#define CP16(dst, src) asm volatile("cp.async.cg.shared.global [%0], [%1], 16;" :: "r"(dst), "l"(src))
#define CP_COMMIT()    asm volatile("cp.async.commit_group;" ::: "memory")
#define CP_WAIT(n)     asm volatile("cp.async.wait_group %0;" :: "n"(n) : "memory")

__device__ __forceinline__ uint32_t packbf2(float a, float b) {
    __nv_bfloat162 h2 = __nv_bfloat162(__float2bfloat16(a), __float2bfloat16(b));
    return *(uint32_t*)&h2;
}

// ---------------------------------------------------------------------------
// Transpose W[K=256,N=256] -> Bt[N,K] with hi/lo split (tiny)
// ---------------------------------------------------------------------------
__global__ void split_bT(const float* __restrict__ W,
                         __nv_bfloat16* __restrict__ hi,
                         __nv_bfloat16* __restrict__ lo) {
    int i = blockIdx.x * blockDim.x + threadIdx.x;
    if (i >= FEAT_ * FEAT_) return;
    int n = i >> 8, k = i & 255;
    float v = W[k * 256 + n];
    __nv_bfloat16 h = __float2bfloat16(v);
    hi[i] = h;
    lo[i] = __float2bfloat16(v - __bfloat162float(h));
}

// ---------------------------------------------------------------------------
// HMMA GEMM (bf16x3 split, fp32 A, fused hi/lo convert, double-buffered)
// + fused attention-dot epilogue: el[n,h], er[n,h] written directly.
// CTA tile 128x128, BK=32, 8 warps each 32x64 (each warp = one head slice).
// ---------------------------------------------------------------------------
#define BKC 32
#define STR 40              // smem row stride in bf16 (80 bytes, conflict-free)
#define TILEB (128 * STR)   // bf16 elements per tile matrix per buffer

__global__ __launch_bounds__(256, 1)
void gemm_bf16x3(const float* __restrict__ A,
                 const __nv_bfloat16* __restrict__ Bhi,
                 const __nv_bfloat16* __restrict__ Blo,
                 float* __restrict__ C,
                 const float* __restrict__ attl,  // [4,64]
                 const float* __restrict__ attr,  // [4,64]
                 float* __restrict__ el,          // [N,4]
                 float* __restrict__ er,          // [N,4]
                 int M) {
    __shared__ __nv_bfloat16 sAh[2][TILEB], sAl[2][TILEB], sBh[2][TILEB], sBl[2][TILEB];

    const int tid = threadIdx.x, wid = tid >> 5, lane = tid & 31;
    const int wm = wid & 3, wn = wid >> 2;
    const int row0 = blockIdx.x * 128;
    const int col0 = blockIdx.y * 128;

    const int sr = tid >> 1, shalf = tid & 1;
    const int agr = row0 + sr;
    const int bgr = col0 + sr;
    const uint32_t sOffB = (uint32_t)(sr * STR * 2 + shalf * 32);

    float acc[2][8][4];
#pragma unroll
    for (int mt = 0; mt < 2; mt++)
#pragma unroll
        for (int nt = 0; nt < 8; nt++)
#pragma unroll
            for (int q = 0; q < 4; q++) acc[mt][nt][q] = 0.f;

    auto stageB = [&](int kc, int buf) {
        const char* srcH = (const char*)(Bhi + (size_t)bgr * 256 + kc * BKC) + shalf * 32;
        const char* srcL = (const char*)(Blo + (size_t)bgr * 256 + kc * BKC) + shalf * 32;
        uint32_t dH = smem_u32(sBh[buf]) + sOffB;
        uint32_t dL = smem_u32(sBl[buf]) + sOffB;
        CP16(dH, srcH); CP16(dH + 16, srcH + 16);
        CP16(dL, srcL); CP16(dL + 16, srcL + 16);
    };
    float fv[16];
    auto loadA = [&](int kc) {
        const float4* ap = (const float4*)(A + (size_t)agr * 256 + kc * BKC) + shalf * 4;
        if (agr < M) {
#pragma unroll
            for (int j = 0; j < 4; j++) *(float4*)(fv + 4 * j) = ap[j];
        } else {
#pragma unroll
            for (int j = 0; j < 16; j++) fv[j] = 0.f;
        }
    };
    auto storeA = [&](int buf) {
        uint32_t hiw[8], low[8];
#pragma unroll
        for (int p = 0; p < 8; p++) {
            float a = fv[2 * p], b = fv[2 * p + 1];
            float ha = __bfloat162float(__float2bfloat16(a));
            float hb = __bfloat162float(__float2bfloat16(b));
            hiw[p] = packbf2(a, b);
            low[p] = packbf2(a - ha, b - hb);
        }
        __nv_bfloat16* dh = sAh[buf] + sr * STR + shalf * 16;
        __nv_bfloat16* dl = sAl[buf] + sr * STR + shalf * 16;
        *(uint4*)dh = make_uint4(hiw[0], hiw[1], hiw[2], hiw[3]);
        *(uint4*)(dh + 8) = make_uint4(hiw[4], hiw[5], hiw[6], hiw[7]);
        *(uint4*)dl = make_uint4(low[0], low[1], low[2], low[3]);
        *(uint4*)(dl + 8) = make_uint4(low[4], low[5], low[6], low[7]);
    };

    const int lrow = lane & 15;
    const int lkof = (lane >> 4) * 8;

    stageB(0, 0); CP_COMMIT();
    loadA(0); storeA(0);

    for (int kc = 0; kc < 8; kc++) {
        const int buf = kc & 1;
        if (kc < 7) {
            stageB(kc + 1, buf ^ 1); CP_COMMIT();
            loadA(kc + 1);
        }
        if (kc < 7) { CP_WAIT(1); } else { CP_WAIT(0); }
        __syncthreads();

        const uint32_t sAh_u = smem_u32(sAh[buf]), sAl_u = smem_u32(sAl[buf]);
        const uint32_t sBh_u = smem_u32(sBh[buf]), sBl_u = smem_u32(sBl[buf]);
#pragma unroll
        for (int ks = 0; ks < 2; ks++) {
            const uint32_t kbyte = (uint32_t)((ks * 16 + lkof) * 2);
            uint32_t ah[2][4], al4[2][4];
#pragma unroll
            for (int mt = 0; mt < 2; mt++) {
                uint32_t ro = (uint32_t)((wm * 32 + mt * 16 + lrow) * STR * 2) + kbyte;
                ldm4(ah[mt], sAh_u + ro);
                ldm4(al4[mt], sAl_u + ro);
            }
            uint32_t bh[4][4], bl[4][4];
#pragma unroll
            for (int p = 0; p < 4; p++) {
                uint32_t ro = (uint32_t)((wn * 64 + p * 16 + lrow) * STR * 2) + kbyte;
                ldm4(bh[p], sBh_u + ro);
                ldm4(bl[p], sBl_u + ro);
            }
#pragma unroll
            for (int mt = 0; mt < 2; mt++)
#pragma unroll
                for (int nt = 0; nt < 8; nt++) {
                    int p = nt >> 1, o = nt & 1;
                    mma16816(acc[mt][nt], ah[mt], bh[p][o], bh[p][2 + o]);
                    mma16816(acc[mt][nt], ah[mt], bl[p][o], bl[p][2 + o]);
                    mma16816(acc[mt][nt], al4[mt], bh[p][o], bh[p][2 + o]);
                }
        }
        __syncthreads();
        if (kc < 7) storeA(buf ^ 1);
    }

    // ---- Epilogue: store C + fused attention dots ----
    const int qrow = lane >> 2, qcol = (lane & 3) * 2;
    const int head = blockIdx.y * 2 + wn;               // this warp's head

    // attention weights for this thread's 16 columns
    float wl[8][2], wr[8][2];
#pragma unroll
    for (int nt = 0; nt < 8; nt++) {
        float2 l2 = *(const float2*)(attl + head * 64 + nt * 8 + qcol);
        float2 r2 = *(const float2*)(attr + head * 64 + nt * 8 + qcol);
        wl[nt][0] = l2.x; wl[nt][1] = l2.y;
        wr[nt][0] = r2.x; wr[nt][1] = r2.y;
    }

#pragma unroll
    for (int mt = 0; mt < 2; mt++) {
        int r0 = row0 + wm * 32 + mt * 16 + qrow;
        float el0 = 0.f, el1 = 0.f, er0 = 0.f, er1 = 0.f;
#pragma unroll
        for (int nt = 0; nt < 8; nt++) {
            int c = col0 + wn * 64 + nt * 8 + qcol;
            if (r0 < M)
                *(float2*)(C + (size_t)r0 * 256 + c) = make_float2(acc[mt][nt][0], acc[mt][nt][1]);
            if (r0 + 8 < M)
                *(float2*)(C + (size_t)(r0 + 8) * 256 + c) = make_float2(acc[mt][nt][2], acc[mt][nt][3]);
            el0 += acc[mt][nt][0] * wl[nt][0] + acc[mt][nt][1] * wl[nt][1];
            el1 += acc[mt][nt][2] * wl[nt][0] + acc[mt][nt][3] * wl[nt][1];
            er0 += acc[mt][nt][0] * wr[nt][0] + acc[mt][nt][1] * wr[nt][1];
            er1 += acc[mt][nt][2] * wr[nt][0] + acc[mt][nt][3] * wr[nt][1];
        }
        // reduce across the 4 lanes of the quad (same row, different qcol)
#pragma unroll
        for (int off = 1; off <= 2; off <<= 1) {
            el0 += __shfl_xor_sync(0xffffffffu, el0, off);
            el1 += __shfl_xor_sync(0xffffffffu, el1, off);
            er0 += __shfl_xor_sync(0xffffffffu, er0, off);
            er1 += __shfl_xor_sync(0xffffffffu, er1, off);
        }
        if ((lane & 3) == 0) {
            if (r0 < M)     { el[r0 * 4 + head] = el0;       er[r0 * 4 + head] = er0; }
            if (r0 + 8 < M) { el[(r0 + 8) * 4 + head] = el1; er[(r0 + 8) * 4 + head] = er1; }
        }
    }
}

// ---------------------------------------------------------------------------
// row_ptr via binary search (dst sorted ascending)
// ---------------------------------------------------------------------------
__global__ void build_rowptr(const int* __restrict__ dst) {
    int i = blockIdx.x * blockDim.x + threadIdx.x;
    if (i > NNODES) return;
    int lo = 0, hi = NEDGES;
    while (lo < hi) {
        int mid = (lo + hi) >> 1;
        if (dst[mid] < i) lo = mid + 1; else hi = mid;
    }
    g_rowptr[i] = lo;
}

// ---------------------------------------------------------------------------
// Fused edge kernel: score + segment softmax + aggregate (+ optional head mean)
// ---------------------------------------------------------------------------
__device__ __forceinline__ float lrelu(float v) { return v > 0.f ? v : SLOPE_ * v; }

template <bool MEAN>
__global__ __launch_bounds__(64)
void edge_fused(const float* __restrict__ hsrc, const int* __restrict__ src,
                const float* __restrict__ el, const float* __restrict__ er,
                const float* __restrict__ bias, float* __restrict__ out) {
    __shared__ float4 s_sc[ECAP];
    __shared__ int    s_src[ECAP];
    __shared__ float4 s_red[64];

    const int n = blockIdx.x, tid = threadIdx.x;
    const int h = tid >> 4, l16 = tid & 15;
    const int b = g_rowptr[n], e1 = g_rowptr[n + 1];
    const int deg = e1 - b;
    const float4 ern = ((const float4*)er)[n];
    const float ern_h = (&ern.x)[h];

    float4 acc = make_float4(0.f, 0.f, 0.f, 0.f);

    if (deg > 0 && deg <= ECAP) {
        for (int i = tid; i < deg; i += 64) {
            int s = src[b + i];
            s_src[i] = s;
            float4 e4 = ((const float4*)el)[s];
            s_sc[i] = make_float4(lrelu(e4.x + ern.x), lrelu(e4.y + ern.y),
                                  lrelu(e4.z + ern.z), lrelu(e4.w + ern.w));
        }
        __syncthreads();
        float m = -CUDART_INF_F;
        for (int i = l16; i < deg; i += 16) m = fmaxf(m, (&s_sc[i].x)[h]);
#pragma unroll
        for (int off = 8; off > 0; off >>= 1)
            m = fmaxf(m, __shfl_xor_sync(0xffffffffu, m, off));
        float s = 0.f;
        for (int i = l16; i < deg; i += 16) s += __expf((&s_sc[i].x)[h] - m);
#pragma unroll
        for (int off = 8; off > 0; off >>= 1)
            s += __shfl_xor_sync(0xffffffffu, s, off);
        float inv = 1.f / s;
        for (int i = l16; i < deg; i += 16)
            (&s_sc[i].x)[h] = __expf((&s_sc[i].x)[h] - m) * inv;
        __syncthreads();
        // aggregate, unrolled x2 for MLP
        int i = 0;
        for (; i + 2 <= deg; i += 2) {
            float a0 = (&s_sc[i].x)[h];
            float a1 = (&s_sc[i + 1].x)[h];
            float4 v0 = ((const float4*)(hsrc + (size_t)s_src[i] * FEAT_))[tid];
            float4 v1 = ((const float4*)(hsrc + (size_t)s_src[i + 1] * FEAT_))[tid];
            acc.x += a0 * v0.x + a1 * v1.x;
            acc.y += a0 * v0.y + a1 * v1.y;
            acc.z += a0 * v0.z + a1 * v1.z;
            acc.w += a0 * v0.w + a1 * v1.w;
        }
        if (i < deg) {
            float a0 = (&s_sc[i].x)[h];
            float4 v0 = ((const float4*)(hsrc + (size_t)s_src[i] * FEAT_))[tid];
            acc.x += a0 * v0.x; acc.y += a0 * v0.y; acc.z += a0 * v0.z; acc.w += a0 * v0.w;
        }
    } else if (deg > ECAP) {
        float m = -CUDART_INF_F;
        for (int i = l16; i < deg; i += 16) {
            int sidx = src[b + i];
            m = fmaxf(m, lrelu(el[sidx * 4 + h] + ern_h));
        }
#pragma unroll
        for (int off = 8; off > 0; off >>= 1)
            m = fmaxf(m, __shfl_xor_sync(0xffffffffu, m, off));
        float s = 0.f;
        for (int i = l16; i < deg; i += 16) {
            int sidx = src[b + i];
            s += __expf(lrelu(el[sidx * 4 + h] + ern_h) - m);
        }
#pragma unroll
        for (int off = 8; off > 0; off >>= 1)
            s += __shfl_xor_sync(0xffffffffu, s, off);
        float inv = 1.f / s;
        for (int i = 0; i < deg; i++) {
            int sidx = src[b + i];
            float a = __expf(lrelu(el[sidx * 4 + h] + ern_h) - m) * inv;
            float4 v = ((const float4*)(hsrc + (size_t)sidx * FEAT_))[tid];
            acc.x += a * v.x; acc.y += a * v.y; acc.z += a * v.z; acc.w += a * v.w;
        }
    }

    float4 bb = ((const float4*)bias)[tid];
    acc.x += bb.x; acc.y += bb.y; acc.z += bb.z; acc.w += bb.w;

    if (!MEAN) {
        ((float4*)(out + (size_t)n * FEAT_))[tid] = acc;
    } else {
        s_red[tid] = acc;
        __syncthreads();
        if (tid < 16) {
            float4 a = s_red[tid], b4 = s_red[tid + 16], c = s_red[tid + 32], d = s_red[tid + 48];
            float4 r = make_float4(0.25f * (a.x + b4.x + c.x + d.x),
                                   0.25f * (a.y + b4.y + c.y + d.y),
                                   0.25f * (a.z + b4.z + c.z + d.z),
                                   0.25f * (a.w + b4.w + c.w + d.w));
            ((float4*)(out + (size_t)n * CDIM_))[tid] = r;
        }
    }
}

// ---------------------------------------------------------------------------
// Launch
// ---------------------------------------------------------------------------
extern "C" void kernel_launch(void* const* d_in, const int* in_sizes, int n_in,
                              void* d_out, int out_size) {
    const float* x   = (const float*)d_in[0];
    const int*   src = (const int*)  d_in[1];
    const int*   dst = (const int*)  d_in[2];
    const float* W1  = (const float*)d_in[3];
    const float* al1 = (const float*)d_in[4];
    const float* ar1 = (const float*)d_in[5];
    const float* b1  = (const float*)d_in[6];
    const float* W2  = (const float*)d_in[7];
    const float* al2 = (const float*)d_in[8];
    const float* ar2 = (const float*)d_in[9];
    const float* b2  = (const float*)d_in[10];
    float* out = (float*)d_out;

    float *h1, *out1, *h2, *el, *er;
    __nv_bfloat16 *Bhi, *Blo;
    cudaGetSymbolAddress((void**)&h1,   g_h1);
    cudaGetSymbolAddress((void**)&out1, g_out1);
    cudaGetSymbolAddress((void**)&h2,   g_h2);
    cudaGetSymbolAddress((void**)&el,   g_el);
    cudaGetSymbolAddress((void**)&er,   g_er);
    cudaGetSymbolAddress((void**)&Bhi,  g_Bhi);
    cudaGetSymbolAddress((void**)&Blo,  g_Blo);

    dim3 gemmGrid(MTILES, 2);

    build_rowptr<<<(NNODES + 256) / 256, 256>>>(dst);

    // ---- Layer 1 ----
    split_bT<<<(FEAT_ * FEAT_ + 255) / 256, 256>>>(W1, Bhi, Blo);
    gemm_bf16x3<<<gemmGrid, 256>>>(x, Bhi, Blo, h1, al1, ar1, el, er, NNODES);
    edge_fused<false><<<NNODES, 64>>>(h1, src, el, er, b1, out1);

    // ---- Layer 2 ----
    split_bT<<<(FEAT_ * FEAT_ + 255) / 256, 256>>>(W2, Bhi, Blo);
    gemm_bf16x3<<<gemmGrid, 256>>>(out1, Bhi, Blo, h2, al2, ar2, el, er, NNODES);
    edge_fused<true><<<NNODES, 64>>>(h2, src, el, er, b2, out);
}

// round 6
// speedup vs baseline: 2.6934x; 1.0127x over previous
#include <cuda_runtime.h>
#include <cuda_bf16.h>
#include <math_constants.h>
#include <cstdint>

// Problem constants
#define NNODES 50000
#define NEDGES 800000
#define HEADS_ 4
#define CDIM_  64
#define SLOPE_ 0.2f
#define FEAT_  256
#define MTILES 391           // ceil(50000/128)
#define ECAP   192           // cached-edge capacity per node (avg deg 16)

// ---------------------------------------------------------------------------
// Scratch
// ---------------------------------------------------------------------------
__device__ __align__(16) float g_h1  [NNODES * FEAT_];
__device__ __align__(16) float g_out1[NNODES * FEAT_];
__device__ __align__(16) float g_h2  [NNODES * FEAT_];
__device__ __align__(16) __nv_bfloat16 g_Bhi[FEAT_ * FEAT_];
__device__ __align__(16) __nv_bfloat16 g_Blo[FEAT_ * FEAT_];
__device__ __align__(16) float g_el  [NNODES * HEADS_];
__device__ __align__(16) float g_er  [NNODES * HEADS_];
__device__ int   g_rowptr[NNODES + 1];

// ---------------------------------------------------------------------------
// PTX helpers (portable ISA: ldmatrix + mma.sync + cp.async)
// ---------------------------------------------------------------------------
__device__ __forceinline__ uint32_t smem_u32(const void* p) {
    uint32_t a;
    asm("{ .reg .u64 t; cvta.to.shared.u64 t, %1; cvt.u32.u64 %0, t; }" : "=r"(a) : "l"(p));
    return a;
}
__device__ __forceinline__ void ldm4(uint32_t* r, uint32_t addr) {
    asm volatile("ldmatrix.sync.aligned.m8n8.x4.shared.b16 {%0,%1,%2,%3}, [%4];"
        : "=r"(r[0]), "=r"(r[1]), "=r"(r[2]), "=r"(r[3]) : "r"(addr));
}
__device__ __forceinline__ void mma16816(float* c, const uint32_t* a, uint32_t b0, uint32_t b1) {
    asm volatile("mma.sync.aligned.m16n8k16.row.col.f32.bf16.bf16.f32 "
        "{%0,%1,%2,%3}, {%4,%5,%6,%7}, {%8,%9}, {%0,%1,%2,%3};"
        : "+f"(c[0]), "+f"(c[1]), "+f"(c[2]), "+f"(c[3])
        : "r"(a[0]), "r"(a[1]), "r"(a[2]), "r"(a[3]), "r"(b0), "r"(b1));
}
#define CP16(dst, src) asm volatile("cp.async.cg.shared.global [%0], [%1], 16;" :: "r"(dst), "l"(src))
#define CP_COMMIT()    asm volatile("cp.async.commit_group;" ::: "memory")
#define CP_WAIT(n)     asm volatile("cp.async.wait_group %0;" :: "n"(n) : "memory")

__device__ __forceinline__ uint32_t packbf2(float a, float b) {
    __nv_bfloat162 h2 = __nv_bfloat162(__float2bfloat16(a), __float2bfloat16(b));
    return *(uint32_t*)&h2;
}

// ---------------------------------------------------------------------------
// Transpose W[K=256,N=256] -> Bt[N,K] with hi/lo split (tiny)
// ---------------------------------------------------------------------------
__global__ void split_bT(const float* __restrict__ W,
                         __nv_bfloat16* __restrict__ hi,
                         __nv_bfloat16* __restrict__ lo) {
    int i = blockIdx.x * blockDim.x + threadIdx.x;
    if (i >= FEAT_ * FEAT_) return;
    int n = i >> 8, k = i & 255;
    float v = W[k * 256 + n];
    __nv_bfloat16 h = __float2bfloat16(v);
    hi[i] = h;
    lo[i] = __float2bfloat16(v - __bfloat162float(h));
}

// ---------------------------------------------------------------------------
// HMMA GEMM (bf16x3 split, fp32 A, fused hi/lo convert, double-buffered)
// + fused attention-dot epilogue. 512 threads, 16 warps each 32(M)x32(N).
// CTA tile 128x128, BK=32.
// ---------------------------------------------------------------------------
#define BKC 32
#define STR 40              // smem row stride in bf16 (80 bytes)
#define TILEB (128 * STR)   // bf16 elements per tile matrix per buffer

__global__ __launch_bounds__(512, 1)
void gemm_bf16x3(const float* __restrict__ A,
                 const __nv_bfloat16* __restrict__ Bhi,
                 const __nv_bfloat16* __restrict__ Blo,
                 float* __restrict__ C,
                 const float* __restrict__ attl,  // [4,64]
                 const float* __restrict__ attr,  // [4,64]
                 float* __restrict__ el,          // [N,4]
                 float* __restrict__ er,          // [N,4]
                 int M) {
    __shared__ __nv_bfloat16 sAh[2][TILEB], sAl[2][TILEB], sBh[2][TILEB], sBl[2][TILEB];
    __shared__ float sEl[128 * 2], sEr[128 * 2];

    const int tid = threadIdx.x, wid = tid >> 5, lane = tid & 31;
    const int wm = wid & 3, wn = wid >> 2;          // warp 32-row / 32-col block
    const int row0 = blockIdx.x * 128;
    const int col0 = blockIdx.y * 128;

    // staging mapping: 4 threads per row
    const int sr = tid >> 2, sq = tid & 3;
    const int agr = row0 + sr;
    const int bgr = col0 + sr;
    const uint32_t sOffB = (uint32_t)(sr * STR * 2 + sq * 16);

    float acc[2][4][4];
#pragma unroll
    for (int mt = 0; mt < 2; mt++)
#pragma unroll
        for (int nt = 0; nt < 4; nt++)
#pragma unroll
            for (int q = 0; q < 4; q++) acc[mt][nt][q] = 0.f;

    auto stageB = [&](int kc, int buf) {
        const char* srcH = (const char*)(Bhi + (size_t)bgr * 256 + kc * BKC) + sq * 16;
        const char* srcL = (const char*)(Blo + (size_t)bgr * 256 + kc * BKC) + sq * 16;
        CP16(smem_u32(sBh[buf]) + sOffB, srcH);
        CP16(smem_u32(sBl[buf]) + sOffB, srcL);
    };
    float fv[8];
    auto loadA = [&](int kc) {
        const float4* ap = (const float4*)(A + (size_t)agr * 256 + kc * BKC) + sq * 2;
        if (agr < M) {
            *(float4*)(fv)     = ap[0];
            *(float4*)(fv + 4) = ap[1];
        } else {
#pragma unroll
            for (int j = 0; j < 8; j++) fv[j] = 0.f;
        }
    };
    auto storeA = [&](int buf) {
        uint32_t hiw[4], low[4];
#pragma unroll
        for (int p = 0; p < 4; p++) {
            float a = fv[2 * p], b = fv[2 * p + 1];
            float ha = __bfloat162float(__float2bfloat16(a));
            float hb = __bfloat162float(__float2bfloat16(b));
            hiw[p] = packbf2(a, b);
            low[p] = packbf2(a - ha, b - hb);
        }
        *(uint4*)(sAh[buf] + sr * STR + sq * 8) = make_uint4(hiw[0], hiw[1], hiw[2], hiw[3]);
        *(uint4*)(sAl[buf] + sr * STR + sq * 8) = make_uint4(low[0], low[1], low[2], low[3]);
    };

    const int lrow = lane & 15;
    const int lkof = (lane >> 4) * 8;

    stageB(0, 0); CP_COMMIT();
    loadA(0); storeA(0);

    for (int kc = 0; kc < 8; kc++) {
        const int buf = kc & 1;
        if (kc < 7) {
            stageB(kc + 1, buf ^ 1); CP_COMMIT();
            loadA(kc + 1);
        }
        if (kc < 7) { CP_WAIT(1); } else { CP_WAIT(0); }
        __syncthreads();

        const uint32_t sAh_u = smem_u32(sAh[buf]), sAl_u = smem_u32(sAl[buf]);
        const uint32_t sBh_u = smem_u32(sBh[buf]), sBl_u = smem_u32(sBl[buf]);
#pragma unroll
        for (int ks = 0; ks < 2; ks++) {
            const uint32_t kbyte = (uint32_t)((ks * 16 + lkof) * 2);
            uint32_t ah[2][4], al4[2][4];
#pragma unroll
            for (int mt = 0; mt < 2; mt++) {
                uint32_t ro = (uint32_t)((wm * 32 + mt * 16 + lrow) * STR * 2) + kbyte;
                ldm4(ah[mt], sAh_u + ro);
                ldm4(al4[mt], sAl_u + ro);
            }
            uint32_t bh[2][4], bl[2][4];
#pragma unroll
            for (int p = 0; p < 2; p++) {
                uint32_t ro = (uint32_t)((wn * 32 + p * 16 + lrow) * STR * 2) + kbyte;
                ldm4(bh[p], sBh_u + ro);
                ldm4(bl[p], sBl_u + ro);
            }
#pragma unroll
            for (int mt = 0; mt < 2; mt++)
#pragma unroll
                for (int nt = 0; nt < 4; nt++) {
                    int p = nt >> 1, o = nt & 1;
                    mma16816(acc[mt][nt], ah[mt], bh[p][o], bh[p][2 + o]);
                    mma16816(acc[mt][nt], ah[mt], bl[p][o], bl[p][2 + o]);
                    mma16816(acc[mt][nt], al4[mt], bh[p][o], bh[p][2 + o]);
                }
        }
        __syncthreads();
        if (kc < 7) storeA(buf ^ 1);
    }

    // ---- Epilogue: store C + fused attention dots ----
    // zero per-row el/er partial buffers
    for (int i = tid; i < 256; i += 512) { sEl[i] = 0.f; sEr[i] = 0.f; }
    __syncthreads();

    const int qrow = lane >> 2, qcol = (lane & 3) * 2;
    const int head_l = wn >> 1;                        // 0 or 1 within this CTA
    const int head = blockIdx.y * 2 + head_l;

    float wl[4][2], wr[4][2];
#pragma unroll
    for (int nt = 0; nt < 4; nt++) {
        int colIdx = (wn & 1) * 32 + nt * 8 + qcol;    // column within head (0..63)
        float2 l2 = *(const float2*)(attl + head * 64 + colIdx);
        float2 r2 = *(const float2*)(attr + head * 64 + colIdx);
        wl[nt][0] = l2.x; wl[nt][1] = l2.y;
        wr[nt][0] = r2.x; wr[nt][1] = r2.y;
    }

#pragma unroll
    for (int mt = 0; mt < 2; mt++) {
        int lr0 = wm * 32 + mt * 16 + qrow;            // local row in tile
        int r0 = row0 + lr0;
        float el0 = 0.f, el1 = 0.f, er0 = 0.f, er1 = 0.f;
#pragma unroll
        for (int nt = 0; nt < 4; nt++) {
            int c = col0 + wn * 32 + nt * 8 + qcol;
            if (r0 < M)
                *(float2*)(C + (size_t)r0 * 256 + c) = make_float2(acc[mt][nt][0], acc[mt][nt][1]);
            if (r0 + 8 < M)
                *(float2*)(C + (size_t)(r0 + 8) * 256 + c) = make_float2(acc[mt][nt][2], acc[mt][nt][3]);
            el0 += acc[mt][nt][0] * wl[nt][0] + acc[mt][nt][1] * wl[nt][1];
            el1 += acc[mt][nt][2] * wl[nt][0] + acc[mt][nt][3] * wl[nt][1];
            er0 += acc[mt][nt][0] * wr[nt][0] + acc[mt][nt][1] * wr[nt][1];
            er1 += acc[mt][nt][2] * wr[nt][0] + acc[mt][nt][3] * wr[nt][1];
        }
#pragma unroll
        for (int off = 1; off <= 2; off <<= 1) {
            el0 += __shfl_xor_sync(0xffffffffu, el0, off);
            el1 += __shfl_xor_sync(0xffffffffu, el1, off);
            er0 += __shfl_xor_sync(0xffffffffu, er0, off);
            er1 += __shfl_xor_sync(0xffffffffu, er1, off);
        }
        if ((lane & 3) == 0) {
            atomicAdd(&sEl[lr0 * 2 + head_l], el0);
            atomicAdd(&sEl[(lr0 + 8) * 2 + head_l], el1);
            atomicAdd(&sEr[lr0 * 2 + head_l], er0);
            atomicAdd(&sEr[(lr0 + 8) * 2 + head_l], er1);
        }
    }
    __syncthreads();
    for (int i = tid; i < 256; i += 512) {
        int row = i >> 1, hl = i & 1;
        int gr = row0 + row;
        if (gr < M) {
            el[gr * 4 + blockIdx.y * 2 + hl] = sEl[i];
            er[gr * 4 + blockIdx.y * 2 + hl] = sEr[i];
        }
    }
}

// ---------------------------------------------------------------------------
// row_ptr via binary search (dst sorted ascending)
// ---------------------------------------------------------------------------
__global__ void build_rowptr(const int* __restrict__ dst) {
    int i = blockIdx.x * blockDim.x + threadIdx.x;
    if (i > NNODES) return;
    int lo = 0, hi = NEDGES;
    while (lo < hi) {
        int mid = (lo + hi) >> 1;
        if (dst[mid] < i) lo = mid + 1; else hi = mid;
    }
    g_rowptr[i] = lo;
}

// ---------------------------------------------------------------------------
// Fused edge kernel: score + segment softmax + aggregate (+ optional head mean)
// ---------------------------------------------------------------------------
__device__ __forceinline__ float lrelu(float v) { return v > 0.f ? v : SLOPE_ * v; }

template <bool MEAN>
__global__ __launch_bounds__(64)
void edge_fused(const float* __restrict__ hsrc, const int* __restrict__ src,
                const float* __restrict__ el, const float* __restrict__ er,
                const float* __restrict__ bias, float* __restrict__ out) {
    __shared__ float4 s_sc[ECAP];
    __shared__ int    s_src[ECAP];
    __shared__ float4 s_red[64];

    const int n = blockIdx.x, tid = threadIdx.x;
    const int h = tid >> 4, l16 = tid & 15;
    const int b = g_rowptr[n], e1 = g_rowptr[n + 1];
    const int deg = e1 - b;
    const float4 ern = ((const float4*)er)[n];
    const float ern_h = (&ern.x)[h];

    float4 acc = make_float4(0.f, 0.f, 0.f, 0.f);

    if (deg > 0 && deg <= ECAP) {
        for (int i = tid; i < deg; i += 64) {
            int s = src[b + i];
            s_src[i] = s;
            float4 e4 = ((const float4*)el)[s];
            s_sc[i] = make_float4(lrelu(e4.x + ern.x), lrelu(e4.y + ern.y),
                                  lrelu(e4.z + ern.z), lrelu(e4.w + ern.w));
        }
        __syncthreads();
        float m = -CUDART_INF_F;
        for (int i = l16; i < deg; i += 16) m = fmaxf(m, (&s_sc[i].x)[h]);
#pragma unroll
        for (int off = 8; off > 0; off >>= 1)
            m = fmaxf(m, __shfl_xor_sync(0xffffffffu, m, off));
        float s = 0.f;
        for (int i = l16; i < deg; i += 16) s += __expf((&s_sc[i].x)[h] - m);
#pragma unroll
        for (int off = 8; off > 0; off >>= 1)
            s += __shfl_xor_sync(0xffffffffu, s, off);
        float inv = 1.f / s;
        for (int i = l16; i < deg; i += 16)
            (&s_sc[i].x)[h] = __expf((&s_sc[i].x)[h] - m) * inv;
        __syncthreads();
        int i = 0;
        for (; i + 2 <= deg; i += 2) {
            float a0 = (&s_sc[i].x)[h];
            float a1 = (&s_sc[i + 1].x)[h];
            float4 v0 = ((const float4*)(hsrc + (size_t)s_src[i] * FEAT_))[tid];
            float4 v1 = ((const float4*)(hsrc + (size_t)s_src[i + 1] * FEAT_))[tid];
            acc.x += a0 * v0.x + a1 * v1.x;
            acc.y += a0 * v0.y + a1 * v1.y;
            acc.z += a0 * v0.z + a1 * v1.z;
            acc.w += a0 * v0.w + a1 * v1.w;
        }
        if (i < deg) {
            float a0 = (&s_sc[i].x)[h];
            float4 v0 = ((const float4*)(hsrc + (size_t)s_src[i] * FEAT_))[tid];
            acc.x += a0 * v0.x; acc.y += a0 * v0.y; acc.z += a0 * v0.z; acc.w += a0 * v0.w;
        }
    } else if (deg > ECAP) {
        float m = -CUDART_INF_F;
        for (int i = l16; i < deg; i += 16) {
            int sidx = src[b + i];
            m = fmaxf(m, lrelu(el[sidx * 4 + h] + ern_h));
        }
#pragma unroll
        for (int off = 8; off > 0; off >>= 1)
            m = fmaxf(m, __shfl_xor_sync(0xffffffffu, m, off));
        float s = 0.f;
        for (int i = l16; i < deg; i += 16) {
            int sidx = src[b + i];
            s += __expf(lrelu(el[sidx * 4 + h] + ern_h) - m);
        }
#pragma unroll
        for (int off = 8; off > 0; off >>= 1)
            s += __shfl_xor_sync(0xffffffffu, s, off);
        float inv = 1.f / s;
        for (int i = 0; i < deg; i++) {
            int sidx = src[b + i];
            float a = __expf(lrelu(el[sidx * 4 + h] + ern_h) - m) * inv;
            float4 v = ((const float4*)(hsrc + (size_t)sidx * FEAT_))[tid];
            acc.x += a * v.x; acc.y += a * v.y; acc.z += a * v.z; acc.w += a * v.w;
        }
    }

    float4 bb = ((const float4*)bias)[tid];
    acc.x += bb.x; acc.y += bb.y; acc.z += bb.z; acc.w += bb.w;

    if (!MEAN) {
        ((float4*)(out + (size_t)n * FEAT_))[tid] = acc;
    } else {
        s_red[tid] = acc;
        __syncthreads();
        if (tid < 16) {
            float4 a = s_red[tid], b4 = s_red[tid + 16], c = s_red[tid + 32], d = s_red[tid + 48];
            float4 r = make_float4(0.25f * (a.x + b4.x + c.x + d.x),
                                   0.25f * (a.y + b4.y + c.y + d.y),
                                   0.25f * (a.z + b4.z + c.z + d.z),
                                   0.25f * (a.w + b4.w + c.w + d.w));
            ((float4*)(out + (size_t)n * CDIM_))[tid] = r;
        }
    }
}

// ---------------------------------------------------------------------------
// Launch
// ---------------------------------------------------------------------------
extern "C" void kernel_launch(void* const* d_in, const int* in_sizes, int n_in,
                              void* d_out, int out_size) {
    const float* x   = (const float*)d_in[0];
    const int*   src = (const int*)  d_in[1];
    const int*   dst = (const int*)  d_in[2];
    const float* W1  = (const float*)d_in[3];
    const float* al1 = (const float*)d_in[4];
    const float* ar1 = (const float*)d_in[5];
    const float* b1  = (const float*)d_in[6];
    const float* W2  = (const float*)d_in[7];
    const float* al2 = (const float*)d_in[8];
    const float* ar2 = (const float*)d_in[9];
    const float* b2  = (const float*)d_in[10];
    float* out = (float*)d_out;

    float *h1, *out1, *h2, *el, *er;
    __nv_bfloat16 *Bhi, *Blo;
    cudaGetSymbolAddress((void**)&h1,   g_h1);
    cudaGetSymbolAddress((void**)&out1, g_out1);
    cudaGetSymbolAddress((void**)&h2,   g_h2);
    cudaGetSymbolAddress((void**)&el,   g_el);
    cudaGetSymbolAddress((void**)&er,   g_er);
    cudaGetSymbolAddress((void**)&Bhi,  g_Bhi);
    cudaGetSymbolAddress((void**)&Blo,  g_Blo);

    dim3 gemmGrid(MTILES, 2);

    build_rowptr<<<(NNODES + 256) / 256, 256>>>(dst);

    // ---- Layer 1 ----
    split_bT<<<(FEAT_ * FEAT_ + 255) / 256, 256>>>(W1, Bhi, Blo);
    gemm_bf16x3<<<gemmGrid, 512>>>(x, Bhi, Blo, h1, al1, ar1, el, er, NNODES);
    edge_fused<false><<<NNODES, 64>>>(h1, src, el, er, b1, out1);

    // ---- Layer 2 ----
    split_bT<<<(FEAT_ * FEAT_ + 255) / 256, 256>>>(W2, Bhi, Blo);
    gemm_bf16x3<<<gemmGrid, 512>>>(out1, Bhi, Blo, h2, al2, ar2, el, er, NNODES);
    edge_fused<true><<<NNODES, 64>>>(h2, src, el, er, b2, out);
}

// round 7
// speedup vs baseline: 2.7844x; 1.0338x over previous
#include <cuda_runtime.h>
#include <cuda_bf16.h>
#include <cuda_fp16.h>
#include <math_constants.h>
#include <cstdint>

// Problem constants
#define NNODES 50000
#define NEDGES 800000
#define HEADS_ 4
#define CDIM_  64
#define SLOPE_ 0.2f
#define FEAT_  256
#define MTILES 391           // ceil(50000/128)
#define ECAP   192           // cached-edge capacity per node (avg deg 16)

// ---------------------------------------------------------------------------
// Scratch
// ---------------------------------------------------------------------------
__device__ __align__(16) __half g_h1  [NNODES * FEAT_];   // fp16 gather source L1
__device__ __align__(16) __half g_h2  [NNODES * FEAT_];   // fp16 gather source L2
__device__ __align__(16) float  g_out1[NNODES * FEAT_];   // fp32 layer-2 GEMM input
__device__ __align__(16) __nv_bfloat16 g_Bhi[FEAT_ * FEAT_];
__device__ __align__(16) __nv_bfloat16 g_Blo[FEAT_ * FEAT_];
__device__ __align__(16) float g_el  [NNODES * HEADS_];
__device__ __align__(16) float g_er  [NNODES * HEADS_];
__device__ int   g_rowptr[NNODES + 1];

// ---------------------------------------------------------------------------
// PTX helpers (portable ISA: ldmatrix + mma.sync + cp.async)
// ---------------------------------------------------------------------------
__device__ __forceinline__ uint32_t smem_u32(const void* p) {
    uint32_t a;
    asm("{ .reg .u64 t; cvta.to.shared.u64 t, %1; cvt.u32.u64 %0, t; }" : "=r"(a) : "l"(p));
    return a;
}
__device__ __forceinline__ void ldm4(uint32_t* r, uint32_t addr) {
    asm volatile("ldmatrix.sync.aligned.m8n8.x4.shared.b16 {%0,%1,%2,%3}, [%4];"
        : "=r"(r[0]), "=r"(r[1]), "=r"(r[2]), "=r"(r[3]) : "r"(addr));
}
__device__ __forceinline__ void mma16816(float* c, const uint32_t* a, uint32_t b0, uint32_t b1) {
    asm volatile("mma.sync.aligned.m16n8k16.row.col.f32.bf16.bf16.f32 "
        "{%0,%1,%2,%3}, {%4,%5,%6,%7}, {%8,%9}, {%0,%1,%2,%3};"
        : "+f"(c[0]), "+f"(c[1]), "+f"(c[2]), "+f"(c[3])
        : "r"(a[0]), "r"(a[1]), "r"(a[2]), "r"(a[3]), "r"(b0), "r"(b1));
}
#define CP16(dst, src) asm volatile("cp.async.cg.shared.global [%0], [%1], 16;" :: "r"(dst), "l"(src))
#define CP_COMMIT()    asm volatile("cp.async.commit_group;" ::: "memory")
#define CP_WAIT(n)     asm volatile("cp.async.wait_group %0;" :: "n"(n) : "memory")

__device__ __forceinline__ uint32_t packbf2(float a, float b) {
    __nv_bfloat162 h2 = __nv_bfloat162(__float2bfloat16(a), __float2bfloat16(b));
    return *(uint32_t*)&h2;
}

// ---------------------------------------------------------------------------
// Transpose W[K=256,N=256] -> Bt[N,K] with hi/lo split (tiny)
// ---------------------------------------------------------------------------
__global__ void split_bT(const float* __restrict__ W,
                         __nv_bfloat16* __restrict__ hi,
                         __nv_bfloat16* __restrict__ lo) {
    int i = blockIdx.x * blockDim.x + threadIdx.x;
    if (i >= FEAT_ * FEAT_) return;
    int n = i >> 8, k = i & 255;
    float v = W[k * 256 + n];
    __nv_bfloat16 h = __float2bfloat16(v);
    hi[i] = h;
    lo[i] = __float2bfloat16(v - __bfloat162float(h));
}

// ---------------------------------------------------------------------------
// HMMA GEMM (bf16x3 split, fp32 A, fused hi/lo convert, double-buffered)
// + fused attention-dot epilogue. 512 threads, 16 warps each 32(M)x32(N).
// C written in fp16 (gather source). CTA tile 128x128, BK=32.
// ---------------------------------------------------------------------------
#define BKC 32
#define STR 40              // smem row stride in bf16 (80 bytes)
#define TILEB (128 * STR)

__global__ __launch_bounds__(512, 1)
void gemm_bf16x3(const float* __restrict__ A,
                 const __nv_bfloat16* __restrict__ Bhi,
                 const __nv_bfloat16* __restrict__ Blo,
                 __half* __restrict__ C,
                 const float* __restrict__ attl,  // [4,64]
                 const float* __restrict__ attr,  // [4,64]
                 float* __restrict__ el,          // [N,4]
                 float* __restrict__ er,          // [N,4]
                 int M) {
    __shared__ __nv_bfloat16 sAh[2][TILEB], sAl[2][TILEB], sBh[2][TILEB], sBl[2][TILEB];
    __shared__ float sEl[128 * 2], sEr[128 * 2];

    const int tid = threadIdx.x, wid = tid >> 5, lane = tid & 31;
    const int wm = wid & 3, wn = wid >> 2;
    const int row0 = blockIdx.x * 128;
    const int col0 = blockIdx.y * 128;

    const int sr = tid >> 2, sq = tid & 3;
    const int agr = row0 + sr;
    const int bgr = col0 + sr;
    const uint32_t sOffB = (uint32_t)(sr * STR * 2 + sq * 16);

    float acc[2][4][4];
#pragma unroll
    for (int mt = 0; mt < 2; mt++)
#pragma unroll
        for (int nt = 0; nt < 4; nt++)
#pragma unroll
            for (int q = 0; q < 4; q++) acc[mt][nt][q] = 0.f;

    auto stageB = [&](int kc, int buf) {
        const char* srcH = (const char*)(Bhi + (size_t)bgr * 256 + kc * BKC) + sq * 16;
        const char* srcL = (const char*)(Blo + (size_t)bgr * 256 + kc * BKC) + sq * 16;
        CP16(smem_u32(sBh[buf]) + sOffB, srcH);
        CP16(smem_u32(sBl[buf]) + sOffB, srcL);
    };
    float fv[8];
    auto loadA = [&](int kc) {
        const float4* ap = (const float4*)(A + (size_t)agr * 256 + kc * BKC) + sq * 2;
        if (agr < M) {
            *(float4*)(fv)     = ap[0];
            *(float4*)(fv + 4) = ap[1];
        } else {
#pragma unroll
            for (int j = 0; j < 8; j++) fv[j] = 0.f;
        }
    };
    auto storeA = [&](int buf) {
        uint32_t hiw[4], low[4];
#pragma unroll
        for (int p = 0; p < 4; p++) {
            float a = fv[2 * p], b = fv[2 * p + 1];
            float ha = __bfloat162float(__float2bfloat16(a));
            float hb = __bfloat162float(__float2bfloat16(b));
            hiw[p] = packbf2(a, b);
            low[p] = packbf2(a - ha, b - hb);
        }
        *(uint4*)(sAh[buf] + sr * STR + sq * 8) = make_uint4(hiw[0], hiw[1], hiw[2], hiw[3]);
        *(uint4*)(sAl[buf] + sr * STR + sq * 8) = make_uint4(low[0], low[1], low[2], low[3]);
    };

    const int lrow = lane & 15;
    const int lkof = (lane >> 4) * 8;

    stageB(0, 0); CP_COMMIT();
    loadA(0); storeA(0);

    for (int kc = 0; kc < 8; kc++) {
        const int buf = kc & 1;
        if (kc < 7) {
            stageB(kc + 1, buf ^ 1); CP_COMMIT();
            loadA(kc + 1);
        }
        if (kc < 7) { CP_WAIT(1); } else { CP_WAIT(0); }
        __syncthreads();

        const uint32_t sAh_u = smem_u32(sAh[buf]), sAl_u = smem_u32(sAl[buf]);
        const uint32_t sBh_u = smem_u32(sBh[buf]), sBl_u = smem_u32(sBl[buf]);
#pragma unroll
        for (int ks = 0; ks < 2; ks++) {
            const uint32_t kbyte = (uint32_t)((ks * 16 + lkof) * 2);
            uint32_t ah[2][4], al4[2][4];
#pragma unroll
            for (int mt = 0; mt < 2; mt++) {
                uint32_t ro = (uint32_t)((wm * 32 + mt * 16 + lrow) * STR * 2) + kbyte;
                ldm4(ah[mt], sAh_u + ro);
                ldm4(al4[mt], sAl_u + ro);
            }
            uint32_t bh[2][4], bl[2][4];
#pragma unroll
            for (int p = 0; p < 2; p++) {
                uint32_t ro = (uint32_t)((wn * 32 + p * 16 + lrow) * STR * 2) + kbyte;
                ldm4(bh[p], sBh_u + ro);
                ldm4(bl[p], sBl_u + ro);
            }
#pragma unroll
            for (int mt = 0; mt < 2; mt++)
#pragma unroll
                for (int nt = 0; nt < 4; nt++) {
                    int p = nt >> 1, o = nt & 1;
                    mma16816(acc[mt][nt], ah[mt], bh[p][o], bh[p][2 + o]);
                    mma16816(acc[mt][nt], ah[mt], bl[p][o], bl[p][2 + o]);
                    mma16816(acc[mt][nt], al4[mt], bh[p][o], bh[p][2 + o]);
                }
        }
        __syncthreads();
        if (kc < 7) storeA(buf ^ 1);
    }

    // ---- Epilogue: store C (fp16) + fused attention dots ----
    for (int i = tid; i < 256; i += 512) { sEl[i] = 0.f; sEr[i] = 0.f; }
    __syncthreads();

    const int qrow = lane >> 2, qcol = (lane & 3) * 2;
    const int head_l = wn >> 1;
    const int head = blockIdx.y * 2 + head_l;

    float wl[4][2], wr[4][2];
#pragma unroll
    for (int nt = 0; nt < 4; nt++) {
        int colIdx = (wn & 1) * 32 + nt * 8 + qcol;
        float2 l2 = *(const float2*)(attl + head * 64 + colIdx);
        float2 r2 = *(const float2*)(attr + head * 64 + colIdx);
        wl[nt][0] = l2.x; wl[nt][1] = l2.y;
        wr[nt][0] = r2.x; wr[nt][1] = r2.y;
    }

#pragma unroll
    for (int mt = 0; mt < 2; mt++) {
        int lr0 = wm * 32 + mt * 16 + qrow;
        int r0 = row0 + lr0;
        float el0 = 0.f, el1 = 0.f, er0 = 0.f, er1 = 0.f;
#pragma unroll
        for (int nt = 0; nt < 4; nt++) {
            int c = col0 + wn * 32 + nt * 8 + qcol;
            if (r0 < M)
                *(__half2*)(C + (size_t)r0 * 256 + c) =
                    __floats2half2_rn(acc[mt][nt][0], acc[mt][nt][1]);
            if (r0 + 8 < M)
                *(__half2*)(C + (size_t)(r0 + 8) * 256 + c) =
                    __floats2half2_rn(acc[mt][nt][2], acc[mt][nt][3]);
            el0 += acc[mt][nt][0] * wl[nt][0] + acc[mt][nt][1] * wl[nt][1];
            el1 += acc[mt][nt][2] * wl[nt][0] + acc[mt][nt][3] * wl[nt][1];
            er0 += acc[mt][nt][0] * wr[nt][0] + acc[mt][nt][1] * wr[nt][1];
            er1 += acc[mt][nt][2] * wr[nt][0] + acc[mt][nt][3] * wr[nt][1];
        }
#pragma unroll
        for (int off = 1; off <= 2; off <<= 1) {
            el0 += __shfl_xor_sync(0xffffffffu, el0, off);
            el1 += __shfl_xor_sync(0xffffffffu, el1, off);
            er0 += __shfl_xor_sync(0xffffffffu, er0, off);
            er1 += __shfl_xor_sync(0xffffffffu, er1, off);
        }
        if ((lane & 3) == 0) {
            atomicAdd(&sEl[lr0 * 2 + head_l], el0);
            atomicAdd(&sEl[(lr0 + 8) * 2 + head_l], el1);
            atomicAdd(&sEr[lr0 * 2 + head_l], er0);
            atomicAdd(&sEr[(lr0 + 8) * 2 + head_l], er1);
        }
    }
    __syncthreads();
    for (int i = tid; i < 256; i += 512) {
        int row = i >> 1, hl = i & 1;
        int gr = row0 + row;
        if (gr < M) {
            el[gr * 4 + blockIdx.y * 2 + hl] = sEl[i];
            er[gr * 4 + blockIdx.y * 2 + hl] = sEr[i];
        }
    }
}

// ---------------------------------------------------------------------------
// row_ptr via binary search (dst sorted ascending)
// ---------------------------------------------------------------------------
__global__ void build_rowptr(const int* __restrict__ dst) {
    int i = blockIdx.x * blockDim.x + threadIdx.x;
    if (i > NNODES) return;
    int lo = 0, hi = NEDGES;
    while (lo < hi) {
        int mid = (lo + hi) >> 1;
        if (dst[mid] < i) lo = mid + 1; else hi = mid;
    }
    g_rowptr[i] = lo;
}

// ---------------------------------------------------------------------------
// Fused edge kernel: score + segment softmax + fp16 gather-aggregate
// 64 threads/node; thread tid owns features [tid*4, tid*4+4) (head = tid>>4).
// ---------------------------------------------------------------------------
__device__ __forceinline__ float lrelu(float v) { return v > 0.f ? v : SLOPE_ * v; }

template <bool MEAN>
__global__ __launch_bounds__(64)
void edge_fused(const __half* __restrict__ hsrc, const int* __restrict__ src,
                const float* __restrict__ el, const float* __restrict__ er,
                const float* __restrict__ bias, float* __restrict__ out) {
    __shared__ float4 s_sc[ECAP];
    __shared__ int    s_src[ECAP];
    __shared__ float4 s_red[64];

    const int n = blockIdx.x, tid = threadIdx.x;
    const int h = tid >> 4, l16 = tid & 15;
    const int b = g_rowptr[n], e1 = g_rowptr[n + 1];
    const int deg = e1 - b;
    const float4 ern = ((const float4*)er)[n];
    const float ern_h = (&ern.x)[h];

    float4 acc = make_float4(0.f, 0.f, 0.f, 0.f);

    if (deg > 0 && deg <= ECAP) {
        for (int i = tid; i < deg; i += 64) {
            int s = src[b + i];
            s_src[i] = s;
            float4 e4 = ((const float4*)el)[s];
            s_sc[i] = make_float4(lrelu(e4.x + ern.x), lrelu(e4.y + ern.y),
                                  lrelu(e4.z + ern.z), lrelu(e4.w + ern.w));
        }
        __syncthreads();
        float m = -CUDART_INF_F;
        for (int i = l16; i < deg; i += 16) m = fmaxf(m, (&s_sc[i].x)[h]);
#pragma unroll
        for (int off = 8; off > 0; off >>= 1)
            m = fmaxf(m, __shfl_xor_sync(0xffffffffu, m, off));
        float s = 0.f;
        for (int i = l16; i < deg; i += 16) s += __expf((&s_sc[i].x)[h] - m);
#pragma unroll
        for (int off = 8; off > 0; off >>= 1)
            s += __shfl_xor_sync(0xffffffffu, s, off);
        float inv = 1.f / s;
        for (int i = l16; i < deg; i += 16)
            (&s_sc[i].x)[h] = __expf((&s_sc[i].x)[h] - m) * inv;
        __syncthreads();
        int i = 0;
        for (; i + 2 <= deg; i += 2) {
            float a0 = (&s_sc[i].x)[h];
            float a1 = (&s_sc[i + 1].x)[h];
            uint2 u0 = ((const uint2*)(hsrc + (size_t)s_src[i] * FEAT_))[tid];
            uint2 u1 = ((const uint2*)(hsrc + (size_t)s_src[i + 1] * FEAT_))[tid];
            float2 p00 = __half22float2(*(__half2*)&u0.x);
            float2 p01 = __half22float2(*(__half2*)&u0.y);
            float2 p10 = __half22float2(*(__half2*)&u1.x);
            float2 p11 = __half22float2(*(__half2*)&u1.y);
            acc.x += a0 * p00.x + a1 * p10.x;
            acc.y += a0 * p00.y + a1 * p10.y;
            acc.z += a0 * p01.x + a1 * p11.x;
            acc.w += a0 * p01.y + a1 * p11.y;
        }
        if (i < deg) {
            float a0 = (&s_sc[i].x)[h];
            uint2 u0 = ((const uint2*)(hsrc + (size_t)s_src[i] * FEAT_))[tid];
            float2 p00 = __half22float2(*(__half2*)&u0.x);
            float2 p01 = __half22float2(*(__half2*)&u0.y);
            acc.x += a0 * p00.x; acc.y += a0 * p00.y;
            acc.z += a0 * p01.x; acc.w += a0 * p01.y;
        }
    } else if (deg > ECAP) {
        float m = -CUDART_INF_F;
        for (int i = l16; i < deg; i += 16) {
            int sidx = src[b + i];
            m = fmaxf(m, lrelu(el[sidx * 4 + h] + ern_h));
        }
#pragma unroll
        for (int off = 8; off > 0; off >>= 1)
            m = fmaxf(m, __shfl_xor_sync(0xffffffffu, m, off));
        float s = 0.f;
        for (int i = l16; i < deg; i += 16) {
            int sidx = src[b + i];
            s += __expf(lrelu(el[sidx * 4 + h] + ern_h) - m);
        }
#pragma unroll
        for (int off = 8; off > 0; off >>= 1)
            s += __shfl_xor_sync(0xffffffffu, s, off);
        float inv = 1.f / s;
        for (int i = 0; i < deg; i++) {
            int sidx = src[b + i];
            float a = __expf(lrelu(el[sidx * 4 + h] + ern_h) - m) * inv;
            uint2 u0 = ((const uint2*)(hsrc + (size_t)sidx * FEAT_))[tid];
            float2 p00 = __half22float2(*(__half2*)&u0.x);
            float2 p01 = __half22float2(*(__half2*)&u0.y);
            acc.x += a * p00.x; acc.y += a * p00.y;
            acc.z += a * p01.x; acc.w += a * p01.y;
        }
    }

    float4 bb = ((const float4*)bias)[tid];
    acc.x += bb.x; acc.y += bb.y; acc.z += bb.z; acc.w += bb.w;

    if (!MEAN) {
        ((float4*)(out + (size_t)n * FEAT_))[tid] = acc;
    } else {
        s_red[tid] = acc;
        __syncthreads();
        if (tid < 16) {
            float4 a = s_red[tid], b4 = s_red[tid + 16], c = s_red[tid + 32], d = s_red[tid + 48];
            float4 r = make_float4(0.25f * (a.x + b4.x + c.x + d.x),
                                   0.25f * (a.y + b4.y + c.y + d.y),
                                   0.25f * (a.z + b4.z + c.z + d.z),
                                   0.25f * (a.w + b4.w + c.w + d.w));
            ((float4*)(out + (size_t)n * CDIM_))[tid] = r;
        }
    }
}

// ---------------------------------------------------------------------------
// Launch
// ---------------------------------------------------------------------------
extern "C" void kernel_launch(void* const* d_in, const int* in_sizes, int n_in,
                              void* d_out, int out_size) {
    const float* x   = (const float*)d_in[0];
    const int*   src = (const int*)  d_in[1];
    const int*   dst = (const int*)  d_in[2];
    const float* W1  = (const float*)d_in[3];
    const float* al1 = (const float*)d_in[4];
    const float* ar1 = (const float*)d_in[5];
    const float* b1  = (const float*)d_in[6];
    const float* W2  = (const float*)d_in[7];
    const float* al2 = (const float*)d_in[8];
    const float* ar2 = (const float*)d_in[9];
    const float* b2  = (const float*)d_in[10];
    float* out = (float*)d_out;

    float *out1, *el, *er;
    __half *h1, *h2;
    __nv_bfloat16 *Bhi, *Blo;
    cudaGetSymbolAddress((void**)&h1,   g_h1);
    cudaGetSymbolAddress((void**)&h2,   g_h2);
    cudaGetSymbolAddress((void**)&out1, g_out1);
    cudaGetSymbolAddress((void**)&el,   g_el);
    cudaGetSymbolAddress((void**)&er,   g_er);
    cudaGetSymbolAddress((void**)&Bhi,  g_Bhi);
    cudaGetSymbolAddress((void**)&Blo,  g_Blo);

    dim3 gemmGrid(MTILES, 2);

    build_rowptr<<<(NNODES + 256) / 256, 256>>>(dst);

    // ---- Layer 1 ----
    split_bT<<<(FEAT_ * FEAT_ + 255) / 256, 256>>>(W1, Bhi, Blo);
    gemm_bf16x3<<<gemmGrid, 512>>>(x, Bhi, Blo, h1, al1, ar1, el, er, NNODES);
    edge_fused<false><<<NNODES, 64>>>(h1, src, el, er, b1, out1);

    // ---- Layer 2 ----
    split_bT<<<(FEAT_ * FEAT_ + 255) / 256, 256>>>(W2, Bhi, Blo);
    gemm_bf16x3<<<gemmGrid, 512>>>(out1, Bhi, Blo, h2, al2, ar2, el, er, NNODES);
    edge_fused<true><<<NNODES, 64>>>(h2, src, el, er, b2, out);
}